// round 7
// baseline (speedup 1.0000x reference)
#include <cuda_runtime.h>

typedef unsigned long long u64;

#define BB 2
#define HH 8
#define SS 4096
#define DD 64
#define HIDN 512
#define NHH 4
#define NCH 256
#define CHK 64

// ---------------- scratch (device globals; no allocations allowed) ----------
__device__ float g_q[BB*HH*SS*DD];
__device__ float g_k[BB*HH*SS*DD];
__device__ float g_v[BB*HH*SS*DD];
__device__ unsigned char g_bq[BB*HH*NHH*SS];
__device__ unsigned char g_bk[BB*HH*NHH*SS];
__device__ int g_sq[BB*HH*NHH*SS];
__device__ int g_sk[BB*HH*NHH*SS];
__device__ int g_undo[BB*HH*NHH*SS];
__device__ float g_osort[BB*HH*NHH*SS*DD];   // 64 MB
__device__ float g_lsort[BB*HH*NHH*SS];

// ---------------- packed f32x2 helpers --------------------------------------
__device__ __forceinline__ void fma2(u64 &d, u64 a, u64 b) {
    asm("fma.rn.f32x2 %0, %1, %2, %0;" : "+l"(d) : "l"(a), "l"(b));
}
__device__ __forceinline__ u64 pack2(float x, float y) {
    u64 r; asm("mov.b64 %0, {%1, %2};" : "=l"(r) : "f"(x), "f"(y)); return r;
}
__device__ __forceinline__ float2 unpack2(u64 a) {
    float x, y; asm("mov.b64 {%0, %1}, %2;" : "=f"(x), "=f"(y) : "l"(a));
    return make_float2(x, y);
}

// ---------------- 1) QKV GEMMs: [8192,512]x[512,512], scatter to [b,h,s,d] --
__global__ __launch_bounds__(256) void gemm_kernel(
        const float* __restrict__ dec, const float* __restrict__ hid,
        const float* __restrict__ wqk, const float* __restrict__ wv) {
    int z = blockIdx.z;
    const float* X = (z == 0) ? dec : hid;
    const float* W = (z == 2) ? wv : wqk;
    float* out = (z == 0) ? g_q : (z == 1) ? g_k : g_v;

    __shared__ float As[16][128];
    __shared__ float Bs[16][64];
    int tid = threadIdx.x;
    int tx = tid & 15, ty = tid >> 4;
    int m0 = blockIdx.y * 128, n0 = blockIdx.x * 64;
    int arow = tid >> 1, acol = (tid & 1) * 8;
    int brow = tid >> 4, bcol = (tid & 15) * 4;

    u64 acc[4][4];
#pragma unroll
    for (int i = 0; i < 4; i++)
#pragma unroll
        for (int j = 0; j < 4; j++) acc[i][j] = 0ULL;

    const float* Abase = X + (size_t)(m0 + arow) * HIDN + acol;
    const float* Bbase = W + (size_t)brow * HIDN + n0 + bcol;

    for (int k0 = 0; k0 < HIDN; k0 += 16) {
        float4 a0 = *(const float4*)(Abase + k0);
        float4 a1 = *(const float4*)(Abase + k0 + 4);
        float4 b0 = *(const float4*)(Bbase + (size_t)k0 * HIDN);
        As[acol+0][arow]=a0.x; As[acol+1][arow]=a0.y; As[acol+2][arow]=a0.z; As[acol+3][arow]=a0.w;
        As[acol+4][arow]=a1.x; As[acol+5][arow]=a1.y; As[acol+6][arow]=a1.z; As[acol+7][arow]=a1.w;
        *(float4*)&Bs[brow][bcol] = b0;
        __syncthreads();
#pragma unroll
        for (int kk = 0; kk < 16; kk++) {
            u64 a2[4];
#pragma unroll
            for (int ii = 0; ii < 4; ii++) a2[ii] = *(const u64*)&As[kk][ty*8 + 2*ii];
            float4 bv = *(const float4*)&Bs[kk][tx*4];
            u64 b2[4] = { pack2(bv.x,bv.x), pack2(bv.y,bv.y), pack2(bv.z,bv.z), pack2(bv.w,bv.w) };
#pragma unroll
            for (int ii = 0; ii < 4; ii++)
#pragma unroll
                for (int j = 0; j < 4; j++) fma2(acc[ii][j], a2[ii], b2[j]);
        }
        __syncthreads();
    }
    int h = n0 >> 6;
#pragma unroll
    for (int ii = 0; ii < 4; ii++) {
        float2 c0 = unpack2(acc[ii][0]), c1 = unpack2(acc[ii][1]);
        float2 c2 = unpack2(acc[ii][2]), c3 = unpack2(acc[ii][3]);
        int m = m0 + ty*8 + 2*ii;
        int b = m >> 12, s = m & (SS - 1);
        float* o0 = out + ((size_t)(b*HH + h)*SS + s)*DD + tx*4;
        *(float4*)o0 = make_float4(c0.x, c1.x, c2.x, c3.x);
        int m1 = m + 1; int b1 = m1 >> 12, s1 = m1 & (SS - 1);
        float* o1 = out + ((size_t)(b1*HH + h)*SS + s1)*DD + tx*4;
        *(float4*)o1 = make_float4(c0.y, c1.y, c2.y, c3.y);
    }
}

// ---------------- 2) LSH hash: buckets = argmax(concat[rv,-rv]) -------------
__global__ __launch_bounds__(128) void hash_kernel(const float* __restrict__ rot) {
    extern __shared__ float rs[];   // [4][64][64]  (n, r, d)
    int tid = threadIdx.x;
    int h = blockIdx.y;
    int b = blockIdx.z >> 1, tensor = blockIdx.z & 1;
    for (int idx = tid; idx < NHH*64*64; idx += 128) {
        int r = idx & 63; int d = (idx >> 6) & 63; int n = idx >> 12;
        rs[(n*64 + r)*64 + d] = rot[(((size_t)h*64 + d)*NHH + n)*64 + r];
    }
    __syncthreads();
    int s = blockIdx.x * 128 + tid;
    const float* vbase = (tensor == 0 ? g_q : g_k) + ((size_t)(b*HH + h)*SS + s)*DD;
    u64 v2[32];
#pragma unroll
    for (int i = 0; i < 32; i++) v2[i] = *(const u64*)(vbase + 2*i);
    unsigned char* outb = (tensor == 0 ? g_bq : g_bk);
    for (int n = 0; n < NHH; n++) {
        float bpv = -1e30f, bnv = -1e30f; int bpi = 0, bni = 0;
        for (int r = 0; r < 64; r++) {
            u64 acc = 0ULL;
            const float* rr = &rs[(n*64 + r)*64];
#pragma unroll
            for (int dp = 0; dp < 32; dp++) fma2(acc, v2[dp], *(const u64*)(rr + 2*dp));
            float2 ac = unpack2(acc);
            float dot = ac.x + ac.y;
            if (dot > bpv)  { bpv = dot;  bpi = r; }
            if (-dot > bnv) { bnv = -dot; bni = r; }
        }
        int bucket = (bpv >= bnv) ? bpi : 64 + bni;   // jnp.argmax first-occurrence
        outb[((size_t)(b*HH + h)*NHH + n)*SS + s] = (unsigned char)bucket;
    }
}

// ---------------- 3) normalize k rows in place (after hashing) --------------
__global__ __launch_bounds__(256) void knorm_kernel() {
    int row = blockIdx.x * 8 + (threadIdx.x >> 5);
    int l = threadIdx.x & 31;
    float* p = g_k + (size_t)row * DD + l*2;
    float2 v = *(float2*)p;
    float ss = v.x*v.x + v.y*v.y;
#pragma unroll
    for (int off = 16; off; off >>= 1) ss += __shfl_xor_sync(0xffffffffu, ss, off);
    float sc = rsqrtf(ss * (1.0f/64.0f) + 1e-6f) * 0.125f;  // * 1/sqrt(D)
    v.x *= sc; v.y *= sc;
    *(float2*)p = v;
}

// ---------------- 4) stable counting sort per (b,h,round,tensor) ------------
__global__ __launch_bounds__(128) void sort_kernel() {
    __shared__ unsigned char sb[SS];
    __shared__ int cnt[128];
    __shared__ int offs[128];
    int combo = blockIdx.x;          // (b*H + h)*NH + n
    int tensor = blockIdx.y;         // 0=q, 1=k
    const unsigned char* bg = (tensor == 0 ? g_bq : g_bk) + (size_t)combo * SS;
    int t = threadIdx.x;
    for (int i = t; i < SS/4; i += 128)
        ((unsigned int*)sb)[i] = ((const unsigned int*)bg)[i];
    __syncthreads();
    int c = 0;
    for (int s2 = 0; s2 < SS; s2++) c += (sb[s2] == (unsigned char)t);
    cnt[t] = c;
    __syncthreads();
    if (t == 0) { int a = 0; for (int i = 0; i < 128; i++) { offs[i] = a; a += cnt[i]; } }
    __syncthreads();
    int off = offs[t];
    int* sorted = (tensor == 0 ? g_sq : g_sk) + (size_t)combo * SS;
    int* undo = g_undo + (size_t)combo * SS;
    for (int s2 = 0; s2 < SS; s2++) {
        if (sb[s2] == (unsigned char)t) {
            sorted[off] = s2;
            if (tensor == 1) undo[s2] = off;
            off++;
        }
    }
}

// ---------------- 5) chunk attention ----------------------------------------
#define QSO 0
#define KSO 4096
#define KSTR 66
#define VTO 12544
#define VSTR 130
#define PRO 0
#define PSTR 130
#define OBO 0
#define OSTR 68
#define IDXO 20864
#define SMEMF 21056

__global__ __launch_bounds__(256, 2) void attn_kernel() {
    extern __shared__ float sm[];
    int tid = threadIdx.x;
    int c = blockIdx.x;          // global chunk 0..255 (ring across rounds)
    int bh = blockIdx.y;         // b*H + h
    int n = c >> 6, cl = c & 63;
    int cp = (c + NCH - 1) & (NCH - 1);
    int np = cp >> 6, clp = cp & 63;

    const int* sq_n = g_sq + ((size_t)bh*NHH + n)*SS + cl*64;
    const int* sq_p = g_sq + ((size_t)bh*NHH + np)*SS + clp*64;
    const int* sk_n = g_sk + ((size_t)bh*NHH + n)*SS + cl*64;
    const int* sk_p = g_sk + ((size_t)bh*NHH + np)*SS + clp*64;

    int* qidx = (int*)&sm[IDXO];
    int* kidx = qidx + 64;
    if (tid < 64)       { int s = sq_n[tid]; qidx[tid] = s; kidx[64 + tid] = s; }
    else if (tid < 128) { kidx[tid - 64] = sq_p[tid - 64]; }

    // q tile [64 x 64]
    {
        int r = tid >> 2, dq = (tid & 3) * 4;
        const float* src = g_q + ((size_t)bh*SS + sq_n[r])*DD;
#pragma unroll
        for (int g = 0; g < 4; g++) {
            int d = dq + g*16;
            *(float4*)&sm[QSO + r*64 + d] = *(const float4*)&src[d];
        }
    }
    // k (normalized) [128 x KSTR], v transposed [64 x VSTR]
    {
        int j = tid >> 1, dbase = (tid & 1) * 32;
        int s = (j < 64) ? sk_p[j] : sk_n[j - 64];
        const float* ksrc = g_k + ((size_t)bh*SS + s)*DD;
        const float* vsrc = g_v + ((size_t)bh*SS + s)*DD;
#pragma unroll
        for (int g2 = 0; g2 < 8; g2++) {
            int d = dbase + g2*4;
            float4 kt = *(const float4*)&ksrc[d];
            *(float2*)&sm[KSO + j*KSTR + d]     = make_float2(kt.x, kt.y);
            *(float2*)&sm[KSO + j*KSTR + d + 2] = make_float2(kt.z, kt.w);
            float4 vt4 = *(const float4*)&vsrc[d];
            sm[VTO + (d+0)*VSTR + j] = vt4.x;
            sm[VTO + (d+1)*VSTR + j] = vt4.y;
            sm[VTO + (d+2)*VSTR + j] = vt4.z;
            sm[VTO + (d+3)*VSTR + j] = vt4.w;
        }
    }
    __syncthreads();

    int w = tid >> 5, l = tid & 31;

    // QK^T: warp w owns rows w*8..w*8+7; lane owns cols l+32*jj
    u64 acc[8][4];
#pragma unroll
    for (int i = 0; i < 8; i++)
#pragma unroll
        for (int j = 0; j < 4; j++) acc[i][j] = 0ULL;
    for (int dp = 0; dp < 32; dp++) {
        u64 k2[4];
#pragma unroll
        for (int jj = 0; jj < 4; jj++) k2[jj] = *(const u64*)&sm[KSO + (l + 32*jj)*KSTR + 2*dp];
#pragma unroll
        for (int rr = 0; rr < 8; rr++) {
            u64 q2 = *(const u64*)&sm[QSO + (w*8 + rr)*64 + 2*dp];
#pragma unroll
            for (int jj = 0; jj < 4; jj++) fma2(acc[rr][jj], q2, k2[jj]);
        }
    }
    __syncthreads();   // q/k tiles free; probs region becomes writable

    // mask + softmax per row; write probs; emit logsumexp
#pragma unroll
    for (int rr = 0; rr < 8; rr++) {
        int i = w*8 + rr;
        int qi = qidx[i];
        float dv[4];
#pragma unroll
        for (int jj = 0; jj < 4; jj++) {
            float2 a = unpack2(acc[rr][jj]);
            float t = a.x + a.y;
            dv[jj] = (qi != kidx[l + 32*jj]) ? t : -1e5f;
        }
        float m = fmaxf(fmaxf(dv[0], dv[1]), fmaxf(dv[2], dv[3]));
#pragma unroll
        for (int off = 16; off; off >>= 1) m = fmaxf(m, __shfl_xor_sync(0xffffffffu, m, off));
        float p[4], ssum = 0.f;
#pragma unroll
        for (int jj = 0; jj < 4; jj++) { p[jj] = expf(dv[jj] - m); ssum += p[jj]; }
#pragma unroll
        for (int off = 16; off; off >>= 1) ssum += __shfl_xor_sync(0xffffffffu, ssum, off);
        float inv = 1.f / ssum;
#pragma unroll
        for (int jj = 0; jj < 4; jj++) sm[PRO + i*PSTR + l + 32*jj] = p[jj] * inv;
        if (l == 0) g_lsort[(size_t)bh*(NHH*SS) + c*64 + i] = logf(ssum) + m;
    }
    __syncthreads();

    // PV: lane owns rows l and l+32; warp owns dims w*8..w*8+7
    u64 o0[8], o1[8];
#pragma unroll
    for (int dd = 0; dd < 8; dd++) { o0[dd] = 0ULL; o1[dd] = 0ULL; }
    for (int jp = 0; jp < 64; jp++) {
        u64 p0 = *(const u64*)&sm[PRO + l*PSTR + 2*jp];
        u64 p1 = *(const u64*)&sm[PRO + (l+32)*PSTR + 2*jp];
#pragma unroll
        for (int dd = 0; dd < 8; dd++) {
            u64 vv = *(const u64*)&sm[VTO + (w*8 + dd)*VSTR + 2*jp];
            fma2(o0[dd], p0, vv);
            fma2(o1[dd], p1, vv);
        }
    }
    __syncthreads();   // probs free; out-stage region writable
#pragma unroll
    for (int dd = 0; dd < 8; dd++) {
        float2 a = unpack2(o0[dd]); sm[OBO + l*OSTR + w*8 + dd] = a.x + a.y;
        float2 b2 = unpack2(o1[dd]); sm[OBO + (l+32)*OSTR + w*8 + dd] = b2.x + b2.y;
    }
    __syncthreads();
    {
        int r = tid >> 2, dq = (tid & 3) * 4;
        float* dst = g_osort + ((size_t)bh*(NHH*SS) + c*64 + r)*DD;
#pragma unroll
        for (int g = 0; g < 4; g++) {
            int d = dq + g*16;
            *(float4*)&dst[d] = *(const float4*)&sm[OBO + r*OSTR + d];
        }
    }
}

// ---------------- 6) key-side undo + combine rounds -------------------------
__global__ __launch_bounds__(256) void combine_kernel(float* __restrict__ out) {
    int row = blockIdx.x * 8 + (threadIdx.x >> 5);  // b*H*S rows
    int l = threadIdx.x & 31;
    int bh = row >> 12;
    int s = row & (SS - 1);
    int b = bh >> 3, h = bh & 7;
    float lg[NHH]; int up[NHH];
#pragma unroll
    for (int n = 0; n < NHH; n++) {
        int u = g_undo[((size_t)bh*NHH + n)*SS + s];
        up[n] = u;
        lg[n] = g_lsort[(size_t)bh*(NHH*SS) + n*SS + u];
    }
    float m = fmaxf(fmaxf(lg[0], lg[1]), fmaxf(lg[2], lg[3]));
    float w[NHH], wsum = 0.f;
#pragma unroll
    for (int n = 0; n < NHH; n++) { w[n] = expf(lg[n] - m); wsum += w[n]; }
    float inv = 1.f / wsum;
    float2 acc = make_float2(0.f, 0.f);
#pragma unroll
    for (int n = 0; n < NHH; n++) {
        float2 o = *(const float2*)&g_osort[((size_t)bh*(NHH*SS) + n*SS + up[n])*DD + l*2];
        acc.x += w[n]*o.x; acc.y += w[n]*o.y;
    }
    acc.x *= inv; acc.y *= inv;
    *(float2*)&out[((size_t)(b*SS + s))*(HH*DD) + h*DD + l*2] = acc;
}

// ---------------- launch -----------------------------------------------------
extern "C" void kernel_launch(void* const* d_in, const int* in_sizes, int n_in,
                              void* d_out, int out_size) {
    const float* dec = (const float*)d_in[0];
    const float* hid = (const float*)d_in[1];
    const float* wqk = (const float*)d_in[2];
    const float* wv  = (const float*)d_in[3];
    const float* rot = (const float*)d_in[4];
    float* out = (float*)d_out;

    cudaFuncSetAttribute(hash_kernel, cudaFuncAttributeMaxDynamicSharedMemorySize, 65536);
    cudaFuncSetAttribute(attn_kernel, cudaFuncAttributeMaxDynamicSharedMemorySize, SMEMF*4);

    gemm_kernel<<<dim3(8, 64, 3), 256>>>(dec, hid, wqk, wv);
    hash_kernel<<<dim3(SS/128, HH, BB*2), 128, 65536>>>(rot);
    knorm_kernel<<<BB*HH*SS/8, 256>>>();
    sort_kernel<<<dim3(BB*HH*NHH, 2), 128>>>();
    attn_kernel<<<dim3(NCH, BB*HH), 256, SMEMF*4>>>();
    combine_kernel<<<BB*HH*SS/8, 256>>>(out);
}

// round 8
// speedup vs baseline: 1.1986x; 1.1986x over previous
#include <cuda_runtime.h>

typedef unsigned long long u64;

#define BB 2
#define HH 8
#define SS 4096
#define DD 64
#define HIDN 512
#define NHH 4
#define NCH 256
#define CHK 64

// ---------------- scratch (device globals; no allocations allowed) ----------
__device__ float g_q[BB*HH*SS*DD];
__device__ float g_k[BB*HH*SS*DD];
__device__ float g_v[BB*HH*SS*DD];
__device__ unsigned char g_bq[BB*HH*NHH*SS];
__device__ unsigned char g_bk[BB*HH*NHH*SS];
__device__ int g_sq[BB*HH*NHH*SS];
__device__ int g_sk[BB*HH*NHH*SS];
__device__ int g_undo[BB*HH*NHH*SS];
__device__ float g_osort[BB*HH*NHH*SS*DD];   // 64 MB
__device__ float g_lsort[BB*HH*NHH*SS];

// ---------------- packed f32x2 helpers --------------------------------------
__device__ __forceinline__ void fma2(u64 &d, u64 a, u64 b) {
    asm("fma.rn.f32x2 %0, %1, %2, %0;" : "+l"(d) : "l"(a), "l"(b));
}
__device__ __forceinline__ u64 pack2(float x, float y) {
    u64 r; asm("mov.b64 %0, {%1, %2};" : "=l"(r) : "f"(x), "f"(y)); return r;
}
__device__ __forceinline__ float2 unpack2(u64 a) {
    float x, y; asm("mov.b64 {%0, %1}, %2;" : "=f"(x), "=f"(y) : "l"(a));
    return make_float2(x, y);
}

// ---------------- 1) QKV GEMMs: [8192,512]x[512,512], scatter to [b,h,s,d] --
__global__ __launch_bounds__(256) void gemm_kernel(
        const float* __restrict__ dec, const float* __restrict__ hid,
        const float* __restrict__ wqk, const float* __restrict__ wv) {
    int z = blockIdx.z;
    const float* X = (z == 0) ? dec : hid;
    const float* W = (z == 2) ? wv : wqk;
    float* out = (z == 0) ? g_q : (z == 1) ? g_k : g_v;

    __shared__ float As[16][128];
    __shared__ float Bs[16][64];
    int tid = threadIdx.x;
    int tx = tid & 15, ty = tid >> 4;
    int m0 = blockIdx.y * 128, n0 = blockIdx.x * 64;
    int arow = tid >> 1, acol = (tid & 1) * 8;
    int brow = tid >> 4, bcol = (tid & 15) * 4;

    u64 acc[4][4];
#pragma unroll
    for (int i = 0; i < 4; i++)
#pragma unroll
        for (int j = 0; j < 4; j++) acc[i][j] = 0ULL;

    const float* Abase = X + (size_t)(m0 + arow) * HIDN + acol;
    const float* Bbase = W + (size_t)brow * HIDN + n0 + bcol;

    for (int k0 = 0; k0 < HIDN; k0 += 16) {
        float4 a0 = *(const float4*)(Abase + k0);
        float4 a1 = *(const float4*)(Abase + k0 + 4);
        float4 b0 = *(const float4*)(Bbase + (size_t)k0 * HIDN);
        As[acol+0][arow]=a0.x; As[acol+1][arow]=a0.y; As[acol+2][arow]=a0.z; As[acol+3][arow]=a0.w;
        As[acol+4][arow]=a1.x; As[acol+5][arow]=a1.y; As[acol+6][arow]=a1.z; As[acol+7][arow]=a1.w;
        *(float4*)&Bs[brow][bcol] = b0;
        __syncthreads();
#pragma unroll
        for (int kk = 0; kk < 16; kk++) {
            u64 a2[4];
#pragma unroll
            for (int ii = 0; ii < 4; ii++) a2[ii] = *(const u64*)&As[kk][ty*8 + 2*ii];
            float4 bv = *(const float4*)&Bs[kk][tx*4];
            u64 b2[4] = { pack2(bv.x,bv.x), pack2(bv.y,bv.y), pack2(bv.z,bv.z), pack2(bv.w,bv.w) };
#pragma unroll
            for (int ii = 0; ii < 4; ii++)
#pragma unroll
                for (int j = 0; j < 4; j++) fma2(acc[ii][j], a2[ii], b2[j]);
        }
        __syncthreads();
    }
    int h = n0 >> 6;
#pragma unroll
    for (int ii = 0; ii < 4; ii++) {
        float2 c0 = unpack2(acc[ii][0]), c1 = unpack2(acc[ii][1]);
        float2 c2 = unpack2(acc[ii][2]), c3 = unpack2(acc[ii][3]);
        int m = m0 + ty*8 + 2*ii;
        int b = m >> 12, s = m & (SS - 1);
        float* o0 = out + ((size_t)(b*HH + h)*SS + s)*DD + tx*4;
        *(float4*)o0 = make_float4(c0.x, c1.x, c2.x, c3.x);
        int m1 = m + 1; int b1 = m1 >> 12, s1 = m1 & (SS - 1);
        float* o1 = out + ((size_t)(b1*HH + h)*SS + s1)*DD + tx*4;
        *(float4*)o1 = make_float4(c0.y, c1.y, c2.y, c3.y);
    }
}

// ---------------- 2) LSH hash as tiled GEMM + fused argmax ------------------
// block: 256 threads, 64-token tile. thread = (tq, tr): tq = tid>>4 owns 4
// tokens; tr = tid&15 -> round n = tr>>2, rgroup rg = tr&3 owns 16 rotations.
#define RSN 4104          // n-stride in floats (64*64 + 8 pad, kills n-bank alias)
#define VSS 65            // v tile token stride
__global__ __launch_bounds__(256) void hash_kernel(const float* __restrict__ rot) {
    extern __shared__ float sh[];
    float* rs = sh;                 // rs[n*RSN + d*64 + r]
    float* vs = sh + NHH*RSN;       // vs[tok*VSS + d]
    int tid = threadIdx.x;
    int h = blockIdx.y;
    int b = blockIdx.z >> 1, tensor = blockIdx.z & 1;

    // rotations: rot[h][d][n][r] contiguous read, transposed store to [n][d][r]
    const float* rsrc = rot + (size_t)h * (64*NHH*64);
    for (int idx = tid; idx < NHH*64*64; idx += 256) {
        int r = idx & 63; int dn = idx >> 6;   // dn = d*NHH + n
        int n = dn & 3, d = dn >> 2;
        rs[n*RSN + d*64 + r] = rsrc[idx];
    }
    int tok0 = blockIdx.x * 64;
    const float* vbase = (tensor == 0 ? g_q : g_k) + ((size_t)(b*HH + h)*SS + tok0)*DD;
    for (int idx = tid; idx < 64*(DD/4); idx += 256) {
        int tok = idx >> 4, d4 = (idx & 15) * 4;
        float4 t4 = *(const float4*)(vbase + tok*DD + d4);
        vs[tok*VSS + d4 + 0] = t4.x; vs[tok*VSS + d4 + 1] = t4.y;
        vs[tok*VSS + d4 + 2] = t4.z; vs[tok*VSS + d4 + 3] = t4.w;
    }
    __syncthreads();

    int tq = tid >> 4, tr = tid & 15;
    int n = tr >> 2, rg = tr & 3;
    const float* rbase = rs + n*RSN + rg*16;

    u64 acc[4][8];
#pragma unroll
    for (int i = 0; i < 4; i++)
#pragma unroll
        for (int j = 0; j < 8; j++) acc[i][j] = 0ULL;

    for (int d = 0; d < 64; d++) {
        u64 b2[8];
        const u64* rp = (const u64*)(rbase + d*64);
#pragma unroll
        for (int j = 0; j < 8; j++) b2[j] = rp[j];
#pragma unroll
        for (int i = 0; i < 4; i++) {
            float vv = vs[(tq*4 + i)*VSS + d];
            u64 a2 = pack2(vv, vv);
#pragma unroll
            for (int j = 0; j < 8; j++) fma2(acc[i][j], a2, b2[j]);
        }
    }

    unsigned char* outb = (tensor == 0 ? g_bq : g_bk);
#pragma unroll
    for (int i = 0; i < 4; i++) {
        float bpv = -1e30f, bnv = -1e30f; int bpi = 0, bni = 0;
#pragma unroll
        for (int j = 0; j < 8; j++) {
            float2 a = unpack2(acc[i][j]);
            int r0 = rg*16 + 2*j;
            if (a.x > bpv)  { bpv = a.x;  bpi = r0; }
            if (a.y > bpv)  { bpv = a.y;  bpi = r0 + 1; }
            if (-a.x > bnv) { bnv = -a.x; bni = r0; }
            if (-a.y > bnv) { bnv = -a.y; bni = r0 + 1; }
        }
        // reduce over rg = 0..3 (contiguous lanes); lower lane = lower r,
        // strict > keeps first occurrence like jnp.argmax
#pragma unroll
        for (int off = 1; off < 4; off <<= 1) {
            float ov = __shfl_down_sync(0xffffffffu, bpv, off);
            int   oi = __shfl_down_sync(0xffffffffu, bpi, off);
            if (ov > bpv) { bpv = ov; bpi = oi; }
            float on = __shfl_down_sync(0xffffffffu, bnv, off);
            int   oj = __shfl_down_sync(0xffffffffu, bni, off);
            if (on > bnv) { bnv = on; bni = oj; }
        }
        if (rg == 0) {
            int bucket = (bpv >= bnv) ? bpi : 64 + bni;  // pos side wins ties
            outb[((size_t)(b*HH + h)*NHH + n)*SS + tok0 + tq*4 + i] = (unsigned char)bucket;
        }
    }
}

// ---------------- 3) warp-parallel stable counting sort ---------------------
__global__ __launch_bounds__(256) void sort_kernel() {
    __shared__ unsigned char sb[SS];
    __shared__ int wcnt[8][128];
    __shared__ int woff[8][128];
    __shared__ int tot[128];
    int combo = blockIdx.x;          // (b*H + h)*NH + n
    int tensor = blockIdx.y;         // 0=q, 1=k
    const unsigned char* bg = (tensor == 0 ? g_bq : g_bk) + (size_t)combo * SS;
    int t = threadIdx.x, w = t >> 5, l = t & 31;
    for (int i = t; i < SS/4; i += 256)
        ((unsigned int*)sb)[i] = ((const unsigned int*)bg)[i];
    if (t < 128) {
#pragma unroll
        for (int ww = 0; ww < 8; ww++) wcnt[ww][t] = 0;
    }
    __syncthreads();
    int seg = w * 512;
    int myb[16];
#pragma unroll
    for (int it = 0; it < 16; it++) {
        int bkt = sb[seg + it*32 + l];
        myb[it] = bkt;
        unsigned mask = __match_any_sync(0xffffffffu, (unsigned)bkt);
        if ((__ffs(mask) - 1) == l) wcnt[w][bkt] += __popc(mask);
    }
    __syncthreads();
    if (t < 128) {
        int s = 0;
#pragma unroll
        for (int ww = 0; ww < 8; ww++) s += wcnt[ww][t];
        tot[t] = s;
    }
    __syncthreads();
    if (t == 0) {
        int a = 0;
        for (int bkt = 0; bkt < 128; bkt++) { int c = tot[bkt]; tot[bkt] = a; a += c; }
    }
    __syncthreads();
    if (t < 128) {
        int run = tot[t];
#pragma unroll
        for (int ww = 0; ww < 8; ww++) { int c = wcnt[ww][t]; woff[ww][t] = run; run += c; }
    }
    __syncthreads();
    int* sorted = (tensor == 0 ? g_sq : g_sk) + (size_t)combo * SS;
    int* undo = g_undo + (size_t)combo * SS;
#pragma unroll
    for (int it = 0; it < 16; it++) {
        int p = seg + it*32 + l;
        int bkt = myb[it];
        unsigned mask = __match_any_sync(0xffffffffu, (unsigned)bkt);
        int leader = __ffs(mask) - 1;
        int rank = __popc(mask & ((1u << l) - 1u));
        int base = 0;
        if (l == leader) { base = woff[w][bkt]; woff[w][bkt] = base + __popc(mask); }
        base = __shfl_sync(mask, base, leader);
        sorted[base + rank] = p;
        if (tensor == 1) undo[p] = base + rank;
    }
}

// ---------------- 4) chunk attention (k-norm fused into load) ---------------
#define QSO 0
#define KSO 4096
#define KSTR 66
#define VTO 12544
#define VSTR 130
#define PRO 0
#define PSTR 130
#define OBO 0
#define OSTR 68
#define IDXO 20864
#define SMEMF 21056

__global__ __launch_bounds__(256, 2) void attn_kernel() {
    extern __shared__ float sm[];
    int tid = threadIdx.x;
    int c = blockIdx.x;          // global chunk 0..255 (ring across rounds)
    int bh = blockIdx.y;         // b*H + h
    int n = c >> 6, cl = c & 63;
    int cp = (c + NCH - 1) & (NCH - 1);
    int np = cp >> 6, clp = cp & 63;

    const int* sq_n = g_sq + ((size_t)bh*NHH + n)*SS + cl*64;
    const int* sq_p = g_sq + ((size_t)bh*NHH + np)*SS + clp*64;
    const int* sk_n = g_sk + ((size_t)bh*NHH + n)*SS + cl*64;
    const int* sk_p = g_sk + ((size_t)bh*NHH + np)*SS + clp*64;

    int* qidx = (int*)&sm[IDXO];
    int* kidx = qidx + 64;
    if (tid < 64)       { int s = sq_n[tid]; qidx[tid] = s; kidx[64 + tid] = s; }
    else if (tid < 128) { kidx[tid - 64] = sq_p[tid - 64]; }

    // q tile [64 x 64]
    {
        int r = tid >> 2, dq = (tid & 3) * 4;
        const float* src = g_q + ((size_t)bh*SS + sq_n[r])*DD;
#pragma unroll
        for (int g = 0; g < 4; g++) {
            int d = dq + g*16;
            *(float4*)&sm[QSO + r*64 + d] = *(const float4*)&src[d];
        }
    }
    // k (normalize on the fly) [128 x KSTR], v transposed [64 x VSTR]
    {
        int j = tid >> 1, dbase = (tid & 1) * 32;
        int s = (j < 64) ? sk_p[j] : sk_n[j - 64];
        const float* ksrc = g_k + ((size_t)bh*SS + s)*DD;
        const float* vsrc = g_v + ((size_t)bh*SS + s)*DD;
        float4 kr[8];
        float ssq = 0.f;
#pragma unroll
        for (int g2 = 0; g2 < 8; g2++) {
            kr[g2] = *(const float4*)&ksrc[dbase + g2*4];
            ssq += kr[g2].x*kr[g2].x + kr[g2].y*kr[g2].y + kr[g2].z*kr[g2].z + kr[g2].w*kr[g2].w;
        }
        ssq += __shfl_xor_sync(0xffffffffu, ssq, 1);   // partner thread, same row
        float sc = rsqrtf(ssq * (1.0f/64.0f) + 1e-6f) * 0.125f;  // * 1/sqrt(D)
#pragma unroll
        for (int g2 = 0; g2 < 8; g2++) {
            int d = dbase + g2*4;
            sm[KSO + j*KSTR + d + 0] = kr[g2].x*sc;
            sm[KSO + j*KSTR + d + 1] = kr[g2].y*sc;
            sm[KSO + j*KSTR + d + 2] = kr[g2].z*sc;
            sm[KSO + j*KSTR + d + 3] = kr[g2].w*sc;
            float4 vt4 = *(const float4*)&vsrc[d];
            sm[VTO + (d+0)*VSTR + j] = vt4.x;
            sm[VTO + (d+1)*VSTR + j] = vt4.y;
            sm[VTO + (d+2)*VSTR + j] = vt4.z;
            sm[VTO + (d+3)*VSTR + j] = vt4.w;
        }
    }
    __syncthreads();

    int w = tid >> 5, l = tid & 31;

    // QK^T: warp w owns rows w*8..w*8+7; lane owns cols l+32*jj
    u64 acc[8][4];
#pragma unroll
    for (int i = 0; i < 8; i++)
#pragma unroll
        for (int j = 0; j < 4; j++) acc[i][j] = 0ULL;
    for (int dp = 0; dp < 32; dp++) {
        u64 k2[4];
#pragma unroll
        for (int jj = 0; jj < 4; jj++) k2[jj] = *(const u64*)&sm[KSO + (l + 32*jj)*KSTR + 2*dp];
#pragma unroll
        for (int rr = 0; rr < 8; rr++) {
            u64 q2 = *(const u64*)&sm[QSO + (w*8 + rr)*64 + 2*dp];
#pragma unroll
            for (int jj = 0; jj < 4; jj++) fma2(acc[rr][jj], q2, k2[jj]);
        }
    }
    __syncthreads();   // q/k tiles free; probs region becomes writable

    // mask + softmax per row; write probs; emit logsumexp
#pragma unroll
    for (int rr = 0; rr < 8; rr++) {
        int i = w*8 + rr;
        int qi = qidx[i];
        float dv[4];
#pragma unroll
        for (int jj = 0; jj < 4; jj++) {
            float2 a = unpack2(acc[rr][jj]);
            float t = a.x + a.y;
            dv[jj] = (qi != kidx[l + 32*jj]) ? t : -1e5f;
        }
        float m = fmaxf(fmaxf(dv[0], dv[1]), fmaxf(dv[2], dv[3]));
#pragma unroll
        for (int off = 16; off; off >>= 1) m = fmaxf(m, __shfl_xor_sync(0xffffffffu, m, off));
        float p[4], ssum = 0.f;
#pragma unroll
        for (int jj = 0; jj < 4; jj++) { p[jj] = expf(dv[jj] - m); ssum += p[jj]; }
#pragma unroll
        for (int off = 16; off; off >>= 1) ssum += __shfl_xor_sync(0xffffffffu, ssum, off);
        float inv = 1.f / ssum;
#pragma unroll
        for (int jj = 0; jj < 4; jj++) sm[PRO + i*PSTR + l + 32*jj] = p[jj] * inv;
        if (l == 0) g_lsort[(size_t)bh*(NHH*SS) + c*64 + i] = logf(ssum) + m;
    }
    __syncthreads();

    // PV: lane owns rows l and l+32; warp owns dims w*8..w*8+7
    u64 o0[8], o1[8];
#pragma unroll
    for (int dd = 0; dd < 8; dd++) { o0[dd] = 0ULL; o1[dd] = 0ULL; }
    for (int jp = 0; jp < 64; jp++) {
        u64 p0 = *(const u64*)&sm[PRO + l*PSTR + 2*jp];
        u64 p1 = *(const u64*)&sm[PRO + (l+32)*PSTR + 2*jp];
#pragma unroll
        for (int dd = 0; dd < 8; dd++) {
            u64 vv = *(const u64*)&sm[VTO + (w*8 + dd)*VSTR + 2*jp];
            fma2(o0[dd], p0, vv);
            fma2(o1[dd], p1, vv);
        }
    }
    __syncthreads();   // probs free; out-stage region writable
#pragma unroll
    for (int dd = 0; dd < 8; dd++) {
        float2 a = unpack2(o0[dd]); sm[OBO + l*OSTR + w*8 + dd] = a.x + a.y;
        float2 b2 = unpack2(o1[dd]); sm[OBO + (l+32)*OSTR + w*8 + dd] = b2.x + b2.y;
    }
    __syncthreads();
    {
        int r = tid >> 2, dq = (tid & 3) * 4;
        float* dst = g_osort + ((size_t)bh*(NHH*SS) + c*64 + r)*DD;
#pragma unroll
        for (int g = 0; g < 4; g++) {
            int d = dq + g*16;
            *(float4*)&dst[d] = *(const float4*)&sm[OBO + r*OSTR + d];
        }
    }
}

// ---------------- 5) key-side undo + combine rounds -------------------------
__global__ __launch_bounds__(256) void combine_kernel(float* __restrict__ out) {
    int row = blockIdx.x * 8 + (threadIdx.x >> 5);  // b*H*S rows
    int l = threadIdx.x & 31;
    int bh = row >> 12;
    int s = row & (SS - 1);
    int b = bh >> 3, h = bh & 7;
    float lg[NHH]; int up[NHH];
#pragma unroll
    for (int n = 0; n < NHH; n++) {
        int u = g_undo[((size_t)bh*NHH + n)*SS + s];
        up[n] = u;
        lg[n] = g_lsort[(size_t)bh*(NHH*SS) + n*SS + u];
    }
    float m = fmaxf(fmaxf(lg[0], lg[1]), fmaxf(lg[2], lg[3]));
    float w[NHH], wsum = 0.f;
#pragma unroll
    for (int n = 0; n < NHH; n++) { w[n] = expf(lg[n] - m); wsum += w[n]; }
    float inv = 1.f / wsum;
    float2 acc = make_float2(0.f, 0.f);
#pragma unroll
    for (int n = 0; n < NHH; n++) {
        float2 o = *(const float2*)&g_osort[((size_t)bh*(NHH*SS) + n*SS + up[n])*DD + l*2];
        acc.x += w[n]*o.x; acc.y += w[n]*o.y;
    }
    acc.x *= inv; acc.y *= inv;
    *(float2*)&out[((size_t)(b*SS + s))*(HH*DD) + h*DD + l*2] = acc;
}

// ---------------- launch -----------------------------------------------------
#define HASH_SMEM ((NHH*RSN + 64*VSS) * 4)

extern "C" void kernel_launch(void* const* d_in, const int* in_sizes, int n_in,
                              void* d_out, int out_size) {
    const float* dec = (const float*)d_in[0];
    const float* hid = (const float*)d_in[1];
    const float* wqk = (const float*)d_in[2];
    const float* wv  = (const float*)d_in[3];
    const float* rot = (const float*)d_in[4];
    float* out = (float*)d_out;

    cudaFuncSetAttribute(hash_kernel, cudaFuncAttributeMaxDynamicSharedMemorySize, HASH_SMEM);
    cudaFuncSetAttribute(attn_kernel, cudaFuncAttributeMaxDynamicSharedMemorySize, SMEMF*4);

    gemm_kernel<<<dim3(8, 64, 3), 256>>>(dec, hid, wqk, wv);
    hash_kernel<<<dim3(SS/64, HH, BB*2), 256, HASH_SMEM>>>(rot);
    sort_kernel<<<dim3(BB*HH*NHH, 2), 256>>>();
    attn_kernel<<<dim3(NCH, BB*HH), 256, SMEMF*4>>>();
    combine_kernel<<<BB*HH*SS/8, 256>>>(out);
}

// round 9
// speedup vs baseline: 1.2161x; 1.0146x over previous
#include <cuda_runtime.h>

typedef unsigned long long u64;

#define BB 2
#define HH 8
#define SS 4096
#define DD 64
#define HIDN 512
#define NHH 4
#define NCH 256
#define CHK 64

// ---------------- scratch (device globals; no allocations allowed) ----------
__device__ float g_q[BB*HH*SS*DD];
__device__ float g_k[BB*HH*SS*DD];
__device__ float g_v[BB*HH*SS*DD];
__device__ unsigned char g_bq[BB*HH*NHH*SS];
__device__ unsigned char g_bk[BB*HH*NHH*SS];
__device__ int g_sq[BB*HH*NHH*SS];
__device__ int g_sk[BB*HH*NHH*SS];
__device__ int g_undo[BB*HH*NHH*SS];
__device__ float g_osort[BB*HH*NHH*SS*DD];   // 64 MB
__device__ float g_lsort[BB*HH*NHH*SS];

// ---------------- packed f32x2 helpers --------------------------------------
__device__ __forceinline__ void fma2(u64 &d, u64 a, u64 b) {
    asm("fma.rn.f32x2 %0, %1, %2, %0;" : "+l"(d) : "l"(a), "l"(b));
}
__device__ __forceinline__ u64 pack2(float x, float y) {
    u64 r; asm("mov.b64 %0, {%1, %2};" : "=l"(r) : "f"(x), "f"(y)); return r;
}
__device__ __forceinline__ float2 unpack2(u64 a) {
    float x, y; asm("mov.b64 {%0, %1}, %2;" : "=f"(x), "=f"(y) : "l"(a));
    return make_float2(x, y);
}

// ---------------- 1) QKV GEMMs: [8192,512]x[512,512], scatter to [b,h,s,d] --
__global__ __launch_bounds__(256) void gemm_kernel(
        const float* __restrict__ dec, const float* __restrict__ hid,
        const float* __restrict__ wqk, const float* __restrict__ wv) {
    int z = blockIdx.z;
    const float* X = (z == 0) ? dec : hid;
    const float* W = (z == 2) ? wv : wqk;
    float* out = (z == 0) ? g_q : (z == 1) ? g_k : g_v;

    __shared__ float As[16][128];
    __shared__ float Bs[16][64];
    int tid = threadIdx.x;
    int tx = tid & 15, ty = tid >> 4;
    int m0 = blockIdx.y * 128, n0 = blockIdx.x * 64;
    int arow = tid >> 1, acol = (tid & 1) * 8;
    int brow = tid >> 4, bcol = (tid & 15) * 4;

    u64 acc[4][4];
#pragma unroll
    for (int i = 0; i < 4; i++)
#pragma unroll
        for (int j = 0; j < 4; j++) acc[i][j] = 0ULL;

    const float* Abase = X + (size_t)(m0 + arow) * HIDN + acol;
    const float* Bbase = W + (size_t)brow * HIDN + n0 + bcol;

    for (int k0 = 0; k0 < HIDN; k0 += 16) {
        float4 a0 = *(const float4*)(Abase + k0);
        float4 a1 = *(const float4*)(Abase + k0 + 4);
        float4 b0 = *(const float4*)(Bbase + (size_t)k0 * HIDN);
        As[acol+0][arow]=a0.x; As[acol+1][arow]=a0.y; As[acol+2][arow]=a0.z; As[acol+3][arow]=a0.w;
        As[acol+4][arow]=a1.x; As[acol+5][arow]=a1.y; As[acol+6][arow]=a1.z; As[acol+7][arow]=a1.w;
        *(float4*)&Bs[brow][bcol] = b0;
        __syncthreads();
#pragma unroll
        for (int kk = 0; kk < 16; kk++) {
            u64 a2[4];
#pragma unroll
            for (int ii = 0; ii < 4; ii++) a2[ii] = *(const u64*)&As[kk][ty*8 + 2*ii];
            float4 bv = *(const float4*)&Bs[kk][tx*4];
            u64 b2[4] = { pack2(bv.x,bv.x), pack2(bv.y,bv.y), pack2(bv.z,bv.z), pack2(bv.w,bv.w) };
#pragma unroll
            for (int ii = 0; ii < 4; ii++)
#pragma unroll
                for (int j = 0; j < 4; j++) fma2(acc[ii][j], a2[ii], b2[j]);
        }
        __syncthreads();
    }
    int h = n0 >> 6;
#pragma unroll
    for (int ii = 0; ii < 4; ii++) {
        float2 c0 = unpack2(acc[ii][0]), c1 = unpack2(acc[ii][1]);
        float2 c2 = unpack2(acc[ii][2]), c3 = unpack2(acc[ii][3]);
        int m = m0 + ty*8 + 2*ii;
        int b = m >> 12, s = m & (SS - 1);
        float* o0 = out + ((size_t)(b*HH + h)*SS + s)*DD + tx*4;
        *(float4*)o0 = make_float4(c0.x, c1.x, c2.x, c3.x);
        int m1 = m + 1; int b1 = m1 >> 12, s1 = m1 & (SS - 1);
        float* o1 = out + ((size_t)(b1*HH + h)*SS + s1)*DD + tx*4;
        *(float4*)o1 = make_float4(c0.y, c1.y, c2.y, c3.y);
    }
}

// ---------------- 2) LSH hash as tiled GEMM + fused argmax ------------------
#define RSN 4104          // n-stride in floats
#define VSS 65            // v tile token stride
__global__ __launch_bounds__(256) void hash_kernel(const float* __restrict__ rot) {
    extern __shared__ float sh[];
    float* rs = sh;                 // rs[n*RSN + d*64 + r]
    float* vs = sh + NHH*RSN;       // vs[tok*VSS + d]
    int tid = threadIdx.x;
    int h = blockIdx.y;
    int b = blockIdx.z >> 1, tensor = blockIdx.z & 1;

    const float* rsrc = rot + (size_t)h * (64*NHH*64);
    for (int idx = tid; idx < NHH*64*64; idx += 256) {
        int r = idx & 63; int dn = idx >> 6;   // dn = d*NHH + n
        int n = dn & 3, d = dn >> 2;
        rs[n*RSN + d*64 + r] = rsrc[idx];
    }
    int tok0 = blockIdx.x * 64;
    const float* vbase = (tensor == 0 ? g_q : g_k) + ((size_t)(b*HH + h)*SS + tok0)*DD;
    for (int idx = tid; idx < 64*(DD/4); idx += 256) {
        int tok = idx >> 4, d4 = (idx & 15) * 4;
        float4 t4 = *(const float4*)(vbase + tok*DD + d4);
        vs[tok*VSS + d4 + 0] = t4.x; vs[tok*VSS + d4 + 1] = t4.y;
        vs[tok*VSS + d4 + 2] = t4.z; vs[tok*VSS + d4 + 3] = t4.w;
    }
    __syncthreads();

    int tq = tid >> 4, tr = tid & 15;
    int n = tr >> 2, rg = tr & 3;
    const float* rbase = rs + n*RSN + rg*16;

    u64 acc[4][8];
#pragma unroll
    for (int i = 0; i < 4; i++)
#pragma unroll
        for (int j = 0; j < 8; j++) acc[i][j] = 0ULL;

    for (int d = 0; d < 64; d++) {
        u64 b2[8];
        const u64* rp = (const u64*)(rbase + d*64);
#pragma unroll
        for (int j = 0; j < 8; j++) b2[j] = rp[j];
#pragma unroll
        for (int i = 0; i < 4; i++) {
            float vv = vs[(tq*4 + i)*VSS + d];
            u64 a2 = pack2(vv, vv);
#pragma unroll
            for (int j = 0; j < 8; j++) fma2(acc[i][j], a2, b2[j]);
        }
    }

    unsigned char* outb = (tensor == 0 ? g_bq : g_bk);
#pragma unroll
    for (int i = 0; i < 4; i++) {
        float bpv = -1e30f, bnv = -1e30f; int bpi = 0, bni = 0;
#pragma unroll
        for (int j = 0; j < 8; j++) {
            float2 a = unpack2(acc[i][j]);
            int r0 = rg*16 + 2*j;
            if (a.x > bpv)  { bpv = a.x;  bpi = r0; }
            if (a.y > bpv)  { bpv = a.y;  bpi = r0 + 1; }
            if (-a.x > bnv) { bnv = -a.x; bni = r0; }
            if (-a.y > bnv) { bnv = -a.y; bni = r0 + 1; }
        }
#pragma unroll
        for (int off = 1; off < 4; off <<= 1) {
            float ov = __shfl_down_sync(0xffffffffu, bpv, off);
            int   oi = __shfl_down_sync(0xffffffffu, bpi, off);
            if (ov > bpv) { bpv = ov; bpi = oi; }
            float on = __shfl_down_sync(0xffffffffu, bnv, off);
            int   oj = __shfl_down_sync(0xffffffffu, bni, off);
            if (on > bnv) { bnv = on; bni = oj; }
        }
        if (rg == 0) {
            int bucket = (bpv >= bnv) ? bpi : 64 + bni;  // pos side wins ties
            outb[((size_t)(b*HH + h)*NHH + n)*SS + tok0 + tq*4 + i] = (unsigned char)bucket;
        }
    }
}

// ---------------- 3) warp-parallel stable counting sort ---------------------
__global__ __launch_bounds__(256) void sort_kernel() {
    __shared__ unsigned char sb[SS];
    __shared__ int wcnt[8][128];
    __shared__ int woff[8][128];
    __shared__ int tot[128];
    int combo = blockIdx.x;
    int tensor = blockIdx.y;
    const unsigned char* bg = (tensor == 0 ? g_bq : g_bk) + (size_t)combo * SS;
    int t = threadIdx.x, w = t >> 5, l = t & 31;
    for (int i = t; i < SS/4; i += 256)
        ((unsigned int*)sb)[i] = ((const unsigned int*)bg)[i];
    if (t < 128) {
#pragma unroll
        for (int ww = 0; ww < 8; ww++) wcnt[ww][t] = 0;
    }
    __syncthreads();
    int seg = w * 512;
    int myb[16];
#pragma unroll
    for (int it = 0; it < 16; it++) {
        int bkt = sb[seg + it*32 + l];
        myb[it] = bkt;
        unsigned mask = __match_any_sync(0xffffffffu, (unsigned)bkt);
        if ((__ffs(mask) - 1) == l) wcnt[w][bkt] += __popc(mask);
    }
    __syncthreads();
    if (t < 128) {
        int s = 0;
#pragma unroll
        for (int ww = 0; ww < 8; ww++) s += wcnt[ww][t];
        tot[t] = s;
    }
    __syncthreads();
    if (t == 0) {
        int a = 0;
        for (int bkt = 0; bkt < 128; bkt++) { int c = tot[bkt]; tot[bkt] = a; a += c; }
    }
    __syncthreads();
    if (t < 128) {
        int run = tot[t];
#pragma unroll
        for (int ww = 0; ww < 8; ww++) { int c = wcnt[ww][t]; woff[ww][t] = run; run += c; }
    }
    __syncthreads();
    int* sorted = (tensor == 0 ? g_sq : g_sk) + (size_t)combo * SS;
    int* undo = g_undo + (size_t)combo * SS;
#pragma unroll
    for (int it = 0; it < 16; it++) {
        int p = seg + it*32 + l;
        int bkt = myb[it];
        unsigned mask = __match_any_sync(0xffffffffu, (unsigned)bkt);
        int leader = __ffs(mask) - 1;
        int rank = __popc(mask & ((1u << l) - 1u));
        int base = 0;
        if (l == leader) { base = woff[w][bkt]; woff[w][bkt] = base + __popc(mask); }
        base = __shfl_sync(mask, base, leader);
        sorted[base + rank] = p;
        if (tensor == 1) undo[p] = base + rank;
    }
}

// ---------------- 4) chunk attention (conflict-free smem layouts) -----------
// QS  [row][d]        floats at QSO, row stride 64
// KT4 [dp2][j] float4 at KTO: float off = KTO + (dp2*128 + j)*4  (dims 4*dp2..)
// VT  [d][j]          floats at VTO, d stride 128
// PB2 [jp][row] u64   at PBO: float off = PBO + (jp*67 + row)*2
// OB  [row][d]        floats at OBO, row stride 68
#define QSO 0
#define KTO 4096
#define VTO 12288
#define PBO 0
#define PBSTR 67
#define OBO 0
#define OSTR 68
#define IDXO 20480
#define SMEMF 20672

__global__ __launch_bounds__(256, 2) void attn_kernel() {
    extern __shared__ float sm[];
    int tid = threadIdx.x;
    int c = blockIdx.x;          // global chunk 0..255 (ring across rounds)
    int bh = blockIdx.y;         // b*H + h
    int n = c >> 6, cl = c & 63;
    int cp = (c + NCH - 1) & (NCH - 1);
    int np = cp >> 6, clp = cp & 63;

    const int* sq_n = g_sq + ((size_t)bh*NHH + n)*SS + cl*64;
    const int* sq_p = g_sq + ((size_t)bh*NHH + np)*SS + clp*64;
    const int* sk_n = g_sk + ((size_t)bh*NHH + n)*SS + cl*64;
    const int* sk_p = g_sk + ((size_t)bh*NHH + np)*SS + clp*64;

    int* qidx = (int*)&sm[IDXO];
    int* kidx = qidx + 64;
    if (tid < 64)       { int s = sq_n[tid]; qidx[tid] = s; kidx[64 + tid] = s; }
    else if (tid < 128) { kidx[tid - 64] = sq_p[tid - 64]; }

    // q tile [64 x 64]
    {
        int r = tid >> 2, dq = (tid & 3) * 4;
        const float* src = g_q + ((size_t)bh*SS + sq_n[r])*DD;
#pragma unroll
        for (int g = 0; g < 4; g++) {
            int d = dq + g*16;
            *(float4*)&sm[QSO + r*64 + d] = *(const float4*)&src[d];
        }
    }
    // K (normalize, dim-major float4 tiles) by threads 0..127; V^T by 128..255
    if (tid < 128) {
        int j = tid;
        int s = (j < 64) ? sk_p[j] : sk_n[j - 64];
        const float4* ksrc = (const float4*)(g_k + ((size_t)bh*SS + s)*DD);
        float ssq = 0.f;
#pragma unroll
        for (int g = 0; g < 16; g++) {
            float4 t = ksrc[g];
            ssq += t.x*t.x + t.y*t.y + t.z*t.z + t.w*t.w;
        }
        float sc = rsqrtf(ssq * (1.0f/64.0f) + 1e-6f) * 0.125f;
#pragma unroll
        for (int g = 0; g < 16; g++) {
            float4 t = ksrc[g];
            *(float4*)&sm[KTO + (g*128 + j)*4] = make_float4(t.x*sc, t.y*sc, t.z*sc, t.w*sc);
        }
    } else {
        int j = tid - 128;
        int s = (j < 64) ? sk_p[j] : sk_n[j - 64];
        const float4* vsrc = (const float4*)(g_v + ((size_t)bh*SS + s)*DD);
#pragma unroll
        for (int g = 0; g < 16; g++) {
            float4 t = vsrc[g];
            sm[VTO + (4*g+0)*128 + j] = t.x;
            sm[VTO + (4*g+1)*128 + j] = t.y;
            sm[VTO + (4*g+2)*128 + j] = t.z;
            sm[VTO + (4*g+3)*128 + j] = t.w;
        }
    }
    __syncthreads();

    int w = tid >> 5, l = tid & 31;

    // QK^T: warp w owns rows w*8..w*8+7; lane owns cols l+32*jj
    u64 acc[8][4];
#pragma unroll
    for (int i = 0; i < 8; i++)
#pragma unroll
        for (int j = 0; j < 4; j++) acc[i][j] = 0ULL;
#pragma unroll 4
    for (int dp2 = 0; dp2 < 16; dp2++) {
        ulonglong2 kk[4];
#pragma unroll
        for (int jj = 0; jj < 4; jj++)
            kk[jj] = *(const ulonglong2*)&sm[KTO + (dp2*128 + l + 32*jj)*4];
#pragma unroll
        for (int rr = 0; rr < 8; rr++) {
            ulonglong2 qq = *(const ulonglong2*)&sm[QSO + (w*8 + rr)*64 + dp2*4];
#pragma unroll
            for (int jj = 0; jj < 4; jj++) {
                fma2(acc[rr][jj], qq.x, kk[jj].x);
                fma2(acc[rr][jj], qq.y, kk[jj].y);
            }
        }
    }
    __syncthreads();   // q/k tiles free; probs region becomes writable

    // mask + softmax per row; write probs transposed-by-pair; emit logsumexp
#pragma unroll
    for (int rr = 0; rr < 8; rr++) {
        int i = w*8 + rr;
        int qi = qidx[i];
        float dv[4];
#pragma unroll
        for (int jj = 0; jj < 4; jj++) {
            float2 a = unpack2(acc[rr][jj]);
            float t = a.x + a.y;
            dv[jj] = (qi != kidx[l + 32*jj]) ? t : -1e5f;
        }
        float m = fmaxf(fmaxf(dv[0], dv[1]), fmaxf(dv[2], dv[3]));
#pragma unroll
        for (int off = 16; off; off >>= 1) m = fmaxf(m, __shfl_xor_sync(0xffffffffu, m, off));
        float p[4], ssum = 0.f;
#pragma unroll
        for (int jj = 0; jj < 4; jj++) { p[jj] = expf(dv[jj] - m); ssum += p[jj]; }
#pragma unroll
        for (int off = 16; off; off >>= 1) ssum += __shfl_xor_sync(0xffffffffu, ssum, off);
        float inv = 1.f / ssum;
#pragma unroll
        for (int jj = 0; jj < 4; jj++) {
            int jp = (l >> 1) + 16*jj;
            sm[PBO + (jp*PBSTR + i)*2 + (l & 1)] = p[jj] * inv;
        }
        if (l == 0) g_lsort[(size_t)bh*(NHH*SS) + c*64 + i] = logf(ssum) + m;
    }
    __syncthreads();

    // PV: lane owns rows l and l+32; warp owns dims w*8..w*8+7
    u64 o0[8], o1[8];
#pragma unroll
    for (int dd = 0; dd < 8; dd++) { o0[dd] = 0ULL; o1[dd] = 0ULL; }
#pragma unroll 4
    for (int jp2 = 0; jp2 < 32; jp2++) {
        u64 pa0 = *(const u64*)&sm[PBO + ((2*jp2)*PBSTR + l)*2];
        u64 pa1 = *(const u64*)&sm[PBO + ((2*jp2)*PBSTR + l + 32)*2];
        u64 pb0 = *(const u64*)&sm[PBO + ((2*jp2+1)*PBSTR + l)*2];
        u64 pb1 = *(const u64*)&sm[PBO + ((2*jp2+1)*PBSTR + l + 32)*2];
#pragma unroll
        for (int dd = 0; dd < 8; dd++) {
            ulonglong2 vv = *(const ulonglong2*)&sm[VTO + (w*8 + dd)*128 + jp2*4];
            fma2(o0[dd], pa0, vv.x);
            fma2(o0[dd], pb0, vv.y);
            fma2(o1[dd], pa1, vv.x);
            fma2(o1[dd], pb1, vv.y);
        }
    }
    __syncthreads();   // probs free; out-stage region writable
#pragma unroll
    for (int dd = 0; dd < 8; dd++) {
        float2 a = unpack2(o0[dd]); sm[OBO + l*OSTR + w*8 + dd] = a.x + a.y;
        float2 b2 = unpack2(o1[dd]); sm[OBO + (l+32)*OSTR + w*8 + dd] = b2.x + b2.y;
    }
    __syncthreads();
    {
        int r = tid >> 2, dq = (tid & 3) * 4;
        float* dst = g_osort + ((size_t)bh*(NHH*SS) + c*64 + r)*DD;
#pragma unroll
        for (int g = 0; g < 4; g++) {
            int d = dq + g*16;
            *(float4*)&dst[d] = *(const float4*)&sm[OBO + r*OSTR + d];
        }
    }
}

// ---------------- 5) key-side undo + combine rounds -------------------------
__global__ __launch_bounds__(256) void combine_kernel(float* __restrict__ out) {
    int row = blockIdx.x * 8 + (threadIdx.x >> 5);  // b*H*S rows
    int l = threadIdx.x & 31;
    int bh = row >> 12;
    int s = row & (SS - 1);
    int b = bh >> 3, h = bh & 7;
    float lg[NHH]; int up[NHH];
#pragma unroll
    for (int n = 0; n < NHH; n++) {
        int u = g_undo[((size_t)bh*NHH + n)*SS + s];
        up[n] = u;
        lg[n] = g_lsort[(size_t)bh*(NHH*SS) + n*SS + u];
    }
    float m = fmaxf(fmaxf(lg[0], lg[1]), fmaxf(lg[2], lg[3]));
    float w[NHH], wsum = 0.f;
#pragma unroll
    for (int n = 0; n < NHH; n++) { w[n] = expf(lg[n] - m); wsum += w[n]; }
    float inv = 1.f / wsum;
    float2 acc = make_float2(0.f, 0.f);
#pragma unroll
    for (int n = 0; n < NHH; n++) {
        float2 o = *(const float2*)&g_osort[((size_t)bh*(NHH*SS) + n*SS + up[n])*DD + l*2];
        acc.x += w[n]*o.x; acc.y += w[n]*o.y;
    }
    acc.x *= inv; acc.y *= inv;
    *(float2*)&out[((size_t)(b*SS + s))*(HH*DD) + h*DD + l*2] = acc;
}

// ---------------- launch -----------------------------------------------------
#define HASH_SMEM ((NHH*RSN + 64*VSS) * 4)

extern "C" void kernel_launch(void* const* d_in, const int* in_sizes, int n_in,
                              void* d_out, int out_size) {
    const float* dec = (const float*)d_in[0];
    const float* hid = (const float*)d_in[1];
    const float* wqk = (const float*)d_in[2];
    const float* wv  = (const float*)d_in[3];
    const float* rot = (const float*)d_in[4];
    float* out = (float*)d_out;

    cudaFuncSetAttribute(hash_kernel, cudaFuncAttributeMaxDynamicSharedMemorySize, HASH_SMEM);
    cudaFuncSetAttribute(attn_kernel, cudaFuncAttributeMaxDynamicSharedMemorySize, SMEMF*4);

    gemm_kernel<<<dim3(8, 64, 3), 256>>>(dec, hid, wqk, wv);
    hash_kernel<<<dim3(SS/64, HH, BB*2), 256, HASH_SMEM>>>(rot);
    sort_kernel<<<dim3(BB*HH*NHH, 2), 256>>>();
    attn_kernel<<<dim3(NCH, BB*HH), 256, SMEMF*4>>>();
    combine_kernel<<<BB*HH*SS/8, 256>>>(out);
}

// round 10
// speedup vs baseline: 1.2321x; 1.0131x over previous
#include <cuda_runtime.h>

typedef unsigned long long u64;

#define BB 2
#define HH 8
#define SS 4096
#define DD 64
#define HIDN 512
#define NHH 4
#define NCH 256
#define CHK 64

// ---------------- scratch (device globals; no allocations allowed) ----------
__device__ float g_q[BB*HH*SS*DD];
__device__ float g_k[BB*HH*SS*DD];
__device__ float g_v[BB*HH*SS*DD];
__device__ unsigned char g_bq[BB*HH*NHH*SS];
__device__ unsigned char g_bk[BB*HH*NHH*SS];
__device__ int g_sq[BB*HH*NHH*SS];
__device__ int g_sk[BB*HH*NHH*SS];
__device__ int g_undo[BB*HH*NHH*SS];
__device__ float g_osort[BB*HH*NHH*SS*DD];   // 64 MB
__device__ float g_lsort[BB*HH*NHH*SS];

// ---------------- packed f32x2 helpers --------------------------------------
__device__ __forceinline__ void fma2(u64 &d, u64 a, u64 b) {
    asm("fma.rn.f32x2 %0, %1, %2, %0;" : "+l"(d) : "l"(a), "l"(b));
}
__device__ __forceinline__ u64 pack2(float x, float y) {
    u64 r; asm("mov.b64 %0, {%1, %2};" : "=l"(r) : "f"(x), "f"(y)); return r;
}
__device__ __forceinline__ float2 unpack2(u64 a) {
    float x, y; asm("mov.b64 {%0, %1}, %2;" : "=f"(x), "=f"(y) : "l"(a));
    return make_float2(x, y);
}

// ---------------- 1) QKV GEMMs: double-buffered, reg-prefetch ---------------
__global__ __launch_bounds__(256) void gemm_kernel(
        const float* __restrict__ dec, const float* __restrict__ hid,
        const float* __restrict__ wqk, const float* __restrict__ wv) {
    int z = blockIdx.z;
    const float* X = (z == 0) ? dec : hid;
    const float* W = (z == 2) ? wv : wqk;
    float* out = (z == 0) ? g_q : (z == 1) ? g_k : g_v;

    __shared__ float As[2][16][128];
    __shared__ float Bs[2][16][64];
    int tid = threadIdx.x;
    int tx = tid & 15, ty = tid >> 4;
    int m0 = blockIdx.y * 128, n0 = blockIdx.x * 64;
    int arow = tid >> 1, acol = (tid & 1) * 8;
    int brow = tid >> 4, bcol = (tid & 15) * 4;

    u64 acc[4][4];
#pragma unroll
    for (int i = 0; i < 4; i++)
#pragma unroll
        for (int j = 0; j < 4; j++) acc[i][j] = 0ULL;

    const float* Abase = X + (size_t)(m0 + arow) * HIDN + acol;
    const float* Bbase = W + (size_t)brow * HIDN + n0 + bcol;

    // prologue: chunk 0 -> buf0; prefetch chunk 1 into regs
    float4 ra0 = *(const float4*)(Abase);
    float4 ra1 = *(const float4*)(Abase + 4);
    float4 rb0 = *(const float4*)(Bbase);
    As[0][acol+0][arow]=ra0.x; As[0][acol+1][arow]=ra0.y; As[0][acol+2][arow]=ra0.z; As[0][acol+3][arow]=ra0.w;
    As[0][acol+4][arow]=ra1.x; As[0][acol+5][arow]=ra1.y; As[0][acol+6][arow]=ra1.z; As[0][acol+7][arow]=ra1.w;
    *(float4*)&Bs[0][brow][bcol] = rb0;
    ra0 = *(const float4*)(Abase + 16);
    ra1 = *(const float4*)(Abase + 20);
    rb0 = *(const float4*)(Bbase + (size_t)16 * HIDN);
    __syncthreads();

    int s = 0;
#pragma unroll 1
    for (int ch = 0; ch < HIDN/16; ch++, s ^= 1) {
        if (ch + 1 < HIDN/16) {   // regs hold chunk ch+1 -> store to other buffer
            int so = s ^ 1;
            As[so][acol+0][arow]=ra0.x; As[so][acol+1][arow]=ra0.y; As[so][acol+2][arow]=ra0.z; As[so][acol+3][arow]=ra0.w;
            As[so][acol+4][arow]=ra1.x; As[so][acol+5][arow]=ra1.y; As[so][acol+6][arow]=ra1.z; As[so][acol+7][arow]=ra1.w;
            *(float4*)&Bs[so][brow][bcol] = rb0;
        }
        if (ch + 2 < HIDN/16) {   // prefetch chunk ch+2 into regs
            int k0 = (ch + 2) * 16;
            ra0 = *(const float4*)(Abase + k0);
            ra1 = *(const float4*)(Abase + k0 + 4);
            rb0 = *(const float4*)(Bbase + (size_t)k0 * HIDN);
        }
#pragma unroll
        for (int kk = 0; kk < 16; kk++) {
            u64 a2[4];
#pragma unroll
            for (int ii = 0; ii < 4; ii++) a2[ii] = *(const u64*)&As[s][kk][ty*8 + 2*ii];
            float4 bv = *(const float4*)&Bs[s][kk][tx*4];
            u64 b2[4] = { pack2(bv.x,bv.x), pack2(bv.y,bv.y), pack2(bv.z,bv.z), pack2(bv.w,bv.w) };
#pragma unroll
            for (int ii = 0; ii < 4; ii++)
#pragma unroll
                for (int j = 0; j < 4; j++) fma2(acc[ii][j], a2[ii], b2[j]);
        }
        __syncthreads();
    }
    int h = n0 >> 6;
#pragma unroll
    for (int ii = 0; ii < 4; ii++) {
        float2 c0 = unpack2(acc[ii][0]), c1 = unpack2(acc[ii][1]);
        float2 c2 = unpack2(acc[ii][2]), c3 = unpack2(acc[ii][3]);
        int m = m0 + ty*8 + 2*ii;
        int b = m >> 12, sx = m & (SS - 1);
        float* o0 = out + ((size_t)(b*HH + h)*SS + sx)*DD + tx*4;
        *(float4*)o0 = make_float4(c0.x, c1.x, c2.x, c3.x);
        int m1 = m + 1; int b1 = m1 >> 12, s1 = m1 & (SS - 1);
        float* o1 = out + ((size_t)(b1*HH + h)*SS + s1)*DD + tx*4;
        *(float4*)o1 = make_float4(c0.y, c1.y, c2.y, c3.y);
    }
}

// ---------------- 2) LSH hash as tiled GEMM + fused argmax ------------------
#define RSN 4104          // n-stride in floats
#define VSS 65            // v tile token stride
__global__ __launch_bounds__(256) void hash_kernel(const float* __restrict__ rot) {
    extern __shared__ float sh[];
    float* rs = sh;                 // rs[n*RSN + d*64 + r]
    float* vs = sh + NHH*RSN;       // vs[tok*VSS + d]
    int tid = threadIdx.x;
    int h = blockIdx.y;
    int b = blockIdx.z >> 1, tensor = blockIdx.z & 1;

    const float* rsrc = rot + (size_t)h * (64*NHH*64);
    for (int idx = tid; idx < NHH*64*64; idx += 256) {
        int r = idx & 63; int dn = idx >> 6;   // dn = d*NHH + n
        int n = dn & 3, d = dn >> 2;
        rs[n*RSN + d*64 + r] = rsrc[idx];
    }
    int tok0 = blockIdx.x * 64;
    const float* vbase = (tensor == 0 ? g_q : g_k) + ((size_t)(b*HH + h)*SS + tok0)*DD;
    for (int idx = tid; idx < 64*(DD/4); idx += 256) {
        int tok = idx >> 4, d4 = (idx & 15) * 4;
        float4 t4 = *(const float4*)(vbase + tok*DD + d4);
        vs[tok*VSS + d4 + 0] = t4.x; vs[tok*VSS + d4 + 1] = t4.y;
        vs[tok*VSS + d4 + 2] = t4.z; vs[tok*VSS + d4 + 3] = t4.w;
    }
    __syncthreads();

    int tq = tid >> 4, tr = tid & 15;
    int n = tr >> 2, rg = tr & 3;
    const float* rbase = rs + n*RSN + rg*16;

    u64 acc[4][8];
#pragma unroll
    for (int i = 0; i < 4; i++)
#pragma unroll
        for (int j = 0; j < 8; j++) acc[i][j] = 0ULL;

    for (int d = 0; d < 64; d++) {
        u64 b2[8];
        const u64* rp = (const u64*)(rbase + d*64);
#pragma unroll
        for (int j = 0; j < 8; j++) b2[j] = rp[j];
#pragma unroll
        for (int i = 0; i < 4; i++) {
            float vv = vs[(tq*4 + i)*VSS + d];
            u64 a2 = pack2(vv, vv);
#pragma unroll
            for (int j = 0; j < 8; j++) fma2(acc[i][j], a2, b2[j]);
        }
    }

    unsigned char* outb = (tensor == 0 ? g_bq : g_bk);
#pragma unroll
    for (int i = 0; i < 4; i++) {
        float bpv = -1e30f, bnv = -1e30f; int bpi = 0, bni = 0;
#pragma unroll
        for (int j = 0; j < 8; j++) {
            float2 a = unpack2(acc[i][j]);
            int r0 = rg*16 + 2*j;
            if (a.x > bpv)  { bpv = a.x;  bpi = r0; }
            if (a.y > bpv)  { bpv = a.y;  bpi = r0 + 1; }
            if (-a.x > bnv) { bnv = -a.x; bni = r0; }
            if (-a.y > bnv) { bnv = -a.y; bni = r0 + 1; }
        }
#pragma unroll
        for (int off = 1; off < 4; off <<= 1) {
            float ov = __shfl_down_sync(0xffffffffu, bpv, off);
            int   oi = __shfl_down_sync(0xffffffffu, bpi, off);
            if (ov > bpv) { bpv = ov; bpi = oi; }
            float on = __shfl_down_sync(0xffffffffu, bnv, off);
            int   oj = __shfl_down_sync(0xffffffffu, bni, off);
            if (on > bnv) { bnv = on; bni = oj; }
        }
        if (rg == 0) {
            int bucket = (bpv >= bnv) ? bpi : 64 + bni;  // pos side wins ties
            outb[((size_t)(b*HH + h)*NHH + n)*SS + tok0 + tq*4 + i] = (unsigned char)bucket;
        }
    }
}

// ---------------- 3) warp-parallel stable counting sort ---------------------
__global__ __launch_bounds__(256) void sort_kernel() {
    __shared__ unsigned char sb[SS];
    __shared__ int wcnt[8][128];
    __shared__ int woff[8][128];
    __shared__ int tot[128];
    int combo = blockIdx.x;
    int tensor = blockIdx.y;
    const unsigned char* bg = (tensor == 0 ? g_bq : g_bk) + (size_t)combo * SS;
    int t = threadIdx.x, w = t >> 5, l = t & 31;
    for (int i = t; i < SS/4; i += 256)
        ((unsigned int*)sb)[i] = ((const unsigned int*)bg)[i];
    if (t < 128) {
#pragma unroll
        for (int ww = 0; ww < 8; ww++) wcnt[ww][t] = 0;
    }
    __syncthreads();
    int seg = w * 512;
    int myb[16];
#pragma unroll
    for (int it = 0; it < 16; it++) {
        int bkt = sb[seg + it*32 + l];
        myb[it] = bkt;
        unsigned mask = __match_any_sync(0xffffffffu, (unsigned)bkt);
        if ((__ffs(mask) - 1) == l) wcnt[w][bkt] += __popc(mask);
    }
    __syncthreads();
    if (t < 128) {
        int s = 0;
#pragma unroll
        for (int ww = 0; ww < 8; ww++) s += wcnt[ww][t];
        tot[t] = s;
    }
    __syncthreads();
    if (t == 0) {
        int a = 0;
        for (int bkt = 0; bkt < 128; bkt++) { int c = tot[bkt]; tot[bkt] = a; a += c; }
    }
    __syncthreads();
    if (t < 128) {
        int run = tot[t];
#pragma unroll
        for (int ww = 0; ww < 8; ww++) { int c = wcnt[ww][t]; woff[ww][t] = run; run += c; }
    }
    __syncthreads();
    int* sorted = (tensor == 0 ? g_sq : g_sk) + (size_t)combo * SS;
    int* undo = g_undo + (size_t)combo * SS;
#pragma unroll
    for (int it = 0; it < 16; it++) {
        int p = seg + it*32 + l;
        int bkt = myb[it];
        unsigned mask = __match_any_sync(0xffffffffu, (unsigned)bkt);
        int leader = __ffs(mask) - 1;
        int rank = __popc(mask & ((1u << l) - 1u));
        int base = 0;
        if (l == leader) { base = woff[w][bkt]; woff[w][bkt] = base + __popc(mask); }
        base = __shfl_sync(mask, base, leader);
        sorted[base + rank] = p;
        if (tensor == 1) undo[p] = base + rank;
    }
}

// ---------------- 4) chunk attention (conflict-free smem layouts) -----------
#define QSO 0
#define KTO 4096
#define VTO 12288
#define PBO 0
#define PBSTR 67
#define OBO 0
#define OSTR 68
#define IDXO 20480
#define SMEMF 20672

__global__ __launch_bounds__(256, 2) void attn_kernel() {
    extern __shared__ float sm[];
    int tid = threadIdx.x;
    int c = blockIdx.x;          // global chunk 0..255 (ring across rounds)
    int bh = blockIdx.y;         // b*H + h
    int n = c >> 6, cl = c & 63;
    int cp = (c + NCH - 1) & (NCH - 1);
    int np = cp >> 6, clp = cp & 63;

    const int* sq_n = g_sq + ((size_t)bh*NHH + n)*SS + cl*64;
    const int* sq_p = g_sq + ((size_t)bh*NHH + np)*SS + clp*64;
    const int* sk_n = g_sk + ((size_t)bh*NHH + n)*SS + cl*64;
    const int* sk_p = g_sk + ((size_t)bh*NHH + np)*SS + clp*64;

    int* qidx = (int*)&sm[IDXO];
    int* kidx = qidx + 64;
    if (tid < 64)       { int s = sq_n[tid]; qidx[tid] = s; kidx[64 + tid] = s; }
    else if (tid < 128) { kidx[tid - 64] = sq_p[tid - 64]; }

    // q tile [64 x 64]
    {
        int r = tid >> 2, dq = (tid & 3) * 4;
        const float* src = g_q + ((size_t)bh*SS + sq_n[r])*DD;
#pragma unroll
        for (int g = 0; g < 4; g++) {
            int d = dq + g*16;
            *(float4*)&sm[QSO + r*64 + d] = *(const float4*)&src[d];
        }
    }
    // K (normalize, dim-major float4 tiles) by threads 0..127; V^T by 128..255
    if (tid < 128) {
        int j = tid;
        int s = (j < 64) ? sk_p[j] : sk_n[j - 64];
        const float4* ksrc = (const float4*)(g_k + ((size_t)bh*SS + s)*DD);
        float ssq = 0.f;
#pragma unroll
        for (int g = 0; g < 16; g++) {
            float4 t = ksrc[g];
            ssq += t.x*t.x + t.y*t.y + t.z*t.z + t.w*t.w;
        }
        float sc = rsqrtf(ssq * (1.0f/64.0f) + 1e-6f) * 0.125f;
#pragma unroll
        for (int g = 0; g < 16; g++) {
            float4 t = ksrc[g];
            *(float4*)&sm[KTO + (g*128 + j)*4] = make_float4(t.x*sc, t.y*sc, t.z*sc, t.w*sc);
        }
    } else {
        int j = tid - 128;
        int s = (j < 64) ? sk_p[j] : sk_n[j - 64];
        const float4* vsrc = (const float4*)(g_v + ((size_t)bh*SS + s)*DD);
#pragma unroll
        for (int g = 0; g < 16; g++) {
            float4 t = vsrc[g];
            sm[VTO + (4*g+0)*128 + j] = t.x;
            sm[VTO + (4*g+1)*128 + j] = t.y;
            sm[VTO + (4*g+2)*128 + j] = t.z;
            sm[VTO + (4*g+3)*128 + j] = t.w;
        }
    }
    __syncthreads();

    int w = tid >> 5, l = tid & 31;

    // QK^T: warp w owns rows w*8..w*8+7; lane owns cols l+32*jj
    u64 acc[8][4];
#pragma unroll
    for (int i = 0; i < 8; i++)
#pragma unroll
        for (int j = 0; j < 4; j++) acc[i][j] = 0ULL;
#pragma unroll 4
    for (int dp2 = 0; dp2 < 16; dp2++) {
        ulonglong2 kk[4];
#pragma unroll
        for (int jj = 0; jj < 4; jj++)
            kk[jj] = *(const ulonglong2*)&sm[KTO + (dp2*128 + l + 32*jj)*4];
#pragma unroll
        for (int rr = 0; rr < 8; rr++) {
            ulonglong2 qq = *(const ulonglong2*)&sm[QSO + (w*8 + rr)*64 + dp2*4];
#pragma unroll
            for (int jj = 0; jj < 4; jj++) {
                fma2(acc[rr][jj], qq.x, kk[jj].x);
                fma2(acc[rr][jj], qq.y, kk[jj].y);
            }
        }
    }
    __syncthreads();   // q/k tiles free; probs region becomes writable

    // mask + softmax per row; write probs transposed-by-pair; emit logsumexp
#pragma unroll
    for (int rr = 0; rr < 8; rr++) {
        int i = w*8 + rr;
        int qi = qidx[i];
        float dv[4];
#pragma unroll
        for (int jj = 0; jj < 4; jj++) {
            float2 a = unpack2(acc[rr][jj]);
            float t = a.x + a.y;
            dv[jj] = (qi != kidx[l + 32*jj]) ? t : -1e5f;
        }
        float m = fmaxf(fmaxf(dv[0], dv[1]), fmaxf(dv[2], dv[3]));
#pragma unroll
        for (int off = 16; off; off >>= 1) m = fmaxf(m, __shfl_xor_sync(0xffffffffu, m, off));
        float p[4], ssum = 0.f;
#pragma unroll
        for (int jj = 0; jj < 4; jj++) { p[jj] = expf(dv[jj] - m); ssum += p[jj]; }
#pragma unroll
        for (int off = 16; off; off >>= 1) ssum += __shfl_xor_sync(0xffffffffu, ssum, off);
        float inv = 1.f / ssum;
#pragma unroll
        for (int jj = 0; jj < 4; jj++) {
            int jp = (l >> 1) + 16*jj;
            sm[PBO + (jp*PBSTR + i)*2 + (l & 1)] = p[jj] * inv;
        }
        if (l == 0) g_lsort[(size_t)bh*(NHH*SS) + c*64 + i] = logf(ssum) + m;
    }
    __syncthreads();

    // PV: lane owns rows l and l+32; warp owns dims w*8..w*8+7
    u64 o0[8], o1[8];
#pragma unroll
    for (int dd = 0; dd < 8; dd++) { o0[dd] = 0ULL; o1[dd] = 0ULL; }
#pragma unroll 4
    for (int jp2 = 0; jp2 < 32; jp2++) {
        u64 pa0 = *(const u64*)&sm[PBO + ((2*jp2)*PBSTR + l)*2];
        u64 pa1 = *(const u64*)&sm[PBO + ((2*jp2)*PBSTR + l + 32)*2];
        u64 pb0 = *(const u64*)&sm[PBO + ((2*jp2+1)*PBSTR + l)*2];
        u64 pb1 = *(const u64*)&sm[PBO + ((2*jp2+1)*PBSTR + l + 32)*2];
#pragma unroll
        for (int dd = 0; dd < 8; dd++) {
            ulonglong2 vv = *(const ulonglong2*)&sm[VTO + (w*8 + dd)*128 + jp2*4];
            fma2(o0[dd], pa0, vv.x);
            fma2(o0[dd], pb0, vv.y);
            fma2(o1[dd], pa1, vv.x);
            fma2(o1[dd], pb1, vv.y);
        }
    }
    __syncthreads();   // probs free; out-stage region writable
#pragma unroll
    for (int dd = 0; dd < 8; dd++) {
        float2 a = unpack2(o0[dd]); sm[OBO + l*OSTR + w*8 + dd] = a.x + a.y;
        float2 b2 = unpack2(o1[dd]); sm[OBO + (l+32)*OSTR + w*8 + dd] = b2.x + b2.y;
    }
    __syncthreads();
    {
        int r = tid >> 2, dq = (tid & 3) * 4;
        float* dst = g_osort + ((size_t)bh*(NHH*SS) + c*64 + r)*DD;
#pragma unroll
        for (int g = 0; g < 4; g++) {
            int d = dq + g*16;
            *(float4*)&dst[d] = *(const float4*)&sm[OBO + r*OSTR + d];
        }
    }
}

// ---------------- 5) key-side undo + combine rounds -------------------------
__global__ __launch_bounds__(256) void combine_kernel(float* __restrict__ out) {
    int row = blockIdx.x * 8 + (threadIdx.x >> 5);  // b*H*S rows
    int l = threadIdx.x & 31;
    int bh = row >> 12;
    int s = row & (SS - 1);
    int b = bh >> 3, h = bh & 7;
    float lg[NHH]; int up[NHH];
#pragma unroll
    for (int n = 0; n < NHH; n++) {
        int u = g_undo[((size_t)bh*NHH + n)*SS + s];
        up[n] = u;
        lg[n] = g_lsort[(size_t)bh*(NHH*SS) + n*SS + u];
    }
    float m = fmaxf(fmaxf(lg[0], lg[1]), fmaxf(lg[2], lg[3]));
    float w[NHH], wsum = 0.f;
#pragma unroll
    for (int n = 0; n < NHH; n++) { w[n] = expf(lg[n] - m); wsum += w[n]; }
    float inv = 1.f / wsum;
    float2 acc = make_float2(0.f, 0.f);
#pragma unroll
    for (int n = 0; n < NHH; n++) {
        float2 o = *(const float2*)&g_osort[((size_t)bh*(NHH*SS) + n*SS + up[n])*DD + l*2];
        acc.x += w[n]*o.x; acc.y += w[n]*o.y;
    }
    acc.x *= inv; acc.y *= inv;
    *(float2*)&out[((size_t)(b*SS + s))*(HH*DD) + h*DD + l*2] = acc;
}

// ---------------- launch -----------------------------------------------------
#define HASH_SMEM ((NHH*RSN + 64*VSS) * 4)

extern "C" void kernel_launch(void* const* d_in, const int* in_sizes, int n_in,
                              void* d_out, int out_size) {
    const float* dec = (const float*)d_in[0];
    const float* hid = (const float*)d_in[1];
    const float* wqk = (const float*)d_in[2];
    const float* wv  = (const float*)d_in[3];
    const float* rot = (const float*)d_in[4];
    float* out = (float*)d_out;

    cudaFuncSetAttribute(hash_kernel, cudaFuncAttributeMaxDynamicSharedMemorySize, HASH_SMEM);
    cudaFuncSetAttribute(attn_kernel, cudaFuncAttributeMaxDynamicSharedMemorySize, SMEMF*4);

    gemm_kernel<<<dim3(8, 64, 3), 256>>>(dec, hid, wqk, wv);
    hash_kernel<<<dim3(SS/64, HH, BB*2), 256, HASH_SMEM>>>(rot);
    sort_kernel<<<dim3(BB*HH*NHH, 2), 256>>>();
    attn_kernel<<<dim3(NCH, BB*HH), 256, SMEMF*4>>>();
    combine_kernel<<<BB*HH*SS/8, 256>>>(out);
}

// round 12
// speedup vs baseline: 1.2382x; 1.0050x over previous
#include <cuda_runtime.h>

typedef unsigned long long u64;

#define BB 2
#define HH 8
#define SS 4096
#define DD 64
#define HIDN 512
#define NHH 4
#define NCH 256
#define CHK 64

// ---------------- scratch (device globals; no allocations allowed) ----------
__device__ float g_q[BB*HH*SS*DD];
__device__ float g_k[BB*HH*SS*DD];
__device__ float g_v[BB*HH*SS*DD];
__device__ unsigned char g_bq[BB*HH*NHH*SS];
__device__ unsigned char g_bk[BB*HH*NHH*SS];
__device__ int g_sq[BB*HH*NHH*SS];
__device__ int g_sk[BB*HH*NHH*SS];
__device__ int g_undo[BB*HH*NHH*SS];
__device__ float g_osort[BB*HH*NHH*SS*DD];   // 64 MB
__device__ float g_lsort[BB*HH*NHH*SS];

// ---------------- packed f32x2 helpers --------------------------------------
__device__ __forceinline__ void fma2(u64 &d, u64 a, u64 b) {
    asm("fma.rn.f32x2 %0, %1, %2, %0;" : "+l"(d) : "l"(a), "l"(b));
}
__device__ __forceinline__ u64 pack2(float x, float y) {
    u64 r; asm("mov.b64 %0, {%1, %2};" : "=l"(r) : "f"(x), "f"(y)); return r;
}
__device__ __forceinline__ float2 unpack2(u64 a) {
    float x, y; asm("mov.b64 {%0, %1}, %2;" : "=f"(x), "=f"(y) : "l"(a));
    return make_float2(x, y);
}

// ---------------- 1) QKV GEMMs: double-buffered, reg-prefetch ---------------
__global__ __launch_bounds__(256) void gemm_kernel(
        const float* __restrict__ dec, const float* __restrict__ hid,
        const float* __restrict__ wqk, const float* __restrict__ wv) {
    int z = blockIdx.z;
    const float* X = (z == 0) ? dec : hid;
    const float* W = (z == 2) ? wv : wqk;
    float* out = (z == 0) ? g_q : (z == 1) ? g_k : g_v;

    __shared__ float As[2][16][128];
    __shared__ float Bs[2][16][64];
    int tid = threadIdx.x;
    int tx = tid & 15, ty = tid >> 4;
    int m0 = blockIdx.y * 128, n0 = blockIdx.x * 64;
    int arow = tid >> 1, acol = (tid & 1) * 8;
    int brow = tid >> 4, bcol = (tid & 15) * 4;

    u64 acc[4][4];
#pragma unroll
    for (int i = 0; i < 4; i++)
#pragma unroll
        for (int j = 0; j < 4; j++) acc[i][j] = 0ULL;

    const float* Abase = X + (size_t)(m0 + arow) * HIDN + acol;
    const float* Bbase = W + (size_t)brow * HIDN + n0 + bcol;

    float4 ra0 = *(const float4*)(Abase);
    float4 ra1 = *(const float4*)(Abase + 4);
    float4 rb0 = *(const float4*)(Bbase);
    As[0][acol+0][arow]=ra0.x; As[0][acol+1][arow]=ra0.y; As[0][acol+2][arow]=ra0.z; As[0][acol+3][arow]=ra0.w;
    As[0][acol+4][arow]=ra1.x; As[0][acol+5][arow]=ra1.y; As[0][acol+6][arow]=ra1.z; As[0][acol+7][arow]=ra1.w;
    *(float4*)&Bs[0][brow][bcol] = rb0;
    ra0 = *(const float4*)(Abase + 16);
    ra1 = *(const float4*)(Abase + 20);
    rb0 = *(const float4*)(Bbase + (size_t)16 * HIDN);
    __syncthreads();

    int s = 0;
#pragma unroll 1
    for (int ch = 0; ch < HIDN/16; ch++, s ^= 1) {
        if (ch + 1 < HIDN/16) {
            int so = s ^ 1;
            As[so][acol+0][arow]=ra0.x; As[so][acol+1][arow]=ra0.y; As[so][acol+2][arow]=ra0.z; As[so][acol+3][arow]=ra0.w;
            As[so][acol+4][arow]=ra1.x; As[so][acol+5][arow]=ra1.y; As[so][acol+6][arow]=ra1.z; As[so][acol+7][arow]=ra1.w;
            *(float4*)&Bs[so][brow][bcol] = rb0;
        }
        if (ch + 2 < HIDN/16) {
            int k0 = (ch + 2) * 16;
            ra0 = *(const float4*)(Abase + k0);
            ra1 = *(const float4*)(Abase + k0 + 4);
            rb0 = *(const float4*)(Bbase + (size_t)k0 * HIDN);
        }
#pragma unroll
        for (int kk = 0; kk < 16; kk++) {
            u64 a2[4];
#pragma unroll
            for (int ii = 0; ii < 4; ii++) a2[ii] = *(const u64*)&As[s][kk][ty*8 + 2*ii];
            float4 bv = *(const float4*)&Bs[s][kk][tx*4];
            u64 b2[4] = { pack2(bv.x,bv.x), pack2(bv.y,bv.y), pack2(bv.z,bv.z), pack2(bv.w,bv.w) };
#pragma unroll
            for (int ii = 0; ii < 4; ii++)
#pragma unroll
                for (int j = 0; j < 4; j++) fma2(acc[ii][j], a2[ii], b2[j]);
        }
        __syncthreads();
    }
    int h = n0 >> 6;
#pragma unroll
    for (int ii = 0; ii < 4; ii++) {
        float2 c0 = unpack2(acc[ii][0]), c1 = unpack2(acc[ii][1]);
        float2 c2 = unpack2(acc[ii][2]), c3 = unpack2(acc[ii][3]);
        int m = m0 + ty*8 + 2*ii;
        int b = m >> 12, sx = m & (SS - 1);
        float* o0 = out + ((size_t)(b*HH + h)*SS + sx)*DD + tx*4;
        *(float4*)o0 = make_float4(c0.x, c1.x, c2.x, c3.x);
        int m1 = m + 1; int b1 = m1 >> 12, s1 = m1 & (SS - 1);
        float* o1 = out + ((size_t)(b1*HH + h)*SS + s1)*DD + tx*4;
        *(float4*)o1 = make_float4(c0.y, c1.y, c2.y, c3.y);
    }
}

// ---------------- 2) LSH hash as tiled GEMM + fused argmax ------------------
#define RSN 4104          // n-stride in floats
#define VSS 65            // v tile token stride
__global__ __launch_bounds__(256) void hash_kernel(const float* __restrict__ rot) {
    extern __shared__ float sh[];
    float* rs = sh;                 // rs[n*RSN + d*64 + r]
    float* vs = sh + NHH*RSN;       // vs[tok*VSS + d]
    int tid = threadIdx.x;
    int h = blockIdx.y;
    int b = blockIdx.z >> 1, tensor = blockIdx.z & 1;

    const float* rsrc = rot + (size_t)h * (64*NHH*64);
    for (int idx = tid; idx < NHH*64*64; idx += 256) {
        int r = idx & 63; int dn = idx >> 6;   // dn = d*NHH + n
        int n = dn & 3, d = dn >> 2;
        rs[n*RSN + d*64 + r] = rsrc[idx];
    }
    int tok0 = blockIdx.x * 64;
    const float* vbase = (tensor == 0 ? g_q : g_k) + ((size_t)(b*HH + h)*SS + tok0)*DD;
    for (int idx = tid; idx < 64*(DD/4); idx += 256) {
        int tok = idx >> 4, d4 = (idx & 15) * 4;
        float4 t4 = *(const float4*)(vbase + tok*DD + d4);
        vs[tok*VSS + d4 + 0] = t4.x; vs[tok*VSS + d4 + 1] = t4.y;
        vs[tok*VSS + d4 + 2] = t4.z; vs[tok*VSS + d4 + 3] = t4.w;
    }
    __syncthreads();

    int tq = tid >> 4, tr = tid & 15;
    int n = tr >> 2, rg = tr & 3;
    const float* rbase = rs + n*RSN + rg*16;

    u64 acc[4][8];
#pragma unroll
    for (int i = 0; i < 4; i++)
#pragma unroll
        for (int j = 0; j < 8; j++) acc[i][j] = 0ULL;

    for (int d = 0; d < 64; d++) {
        u64 b2[8];
        const u64* rp = (const u64*)(rbase + d*64);
#pragma unroll
        for (int j = 0; j < 8; j++) b2[j] = rp[j];
#pragma unroll
        for (int i = 0; i < 4; i++) {
            float vv = vs[(tq*4 + i)*VSS + d];
            u64 a2 = pack2(vv, vv);
#pragma unroll
            for (int j = 0; j < 8; j++) fma2(acc[i][j], a2, b2[j]);
        }
    }

    unsigned char* outb = (tensor == 0 ? g_bq : g_bk);
#pragma unroll
    for (int i = 0; i < 4; i++) {
        float bpv = -1e30f, bnv = -1e30f; int bpi = 0, bni = 0;
#pragma unroll
        for (int j = 0; j < 8; j++) {
            float2 a = unpack2(acc[i][j]);
            int r0 = rg*16 + 2*j;
            if (a.x > bpv)  { bpv = a.x;  bpi = r0; }
            if (a.y > bpv)  { bpv = a.y;  bpi = r0 + 1; }
            if (-a.x > bnv) { bnv = -a.x; bni = r0; }
            if (-a.y > bnv) { bnv = -a.y; bni = r0 + 1; }
        }
#pragma unroll
        for (int off = 1; off < 4; off <<= 1) {
            float ov = __shfl_down_sync(0xffffffffu, bpv, off);
            int   oi = __shfl_down_sync(0xffffffffu, bpi, off);
            if (ov > bpv) { bpv = ov; bpi = oi; }
            float on = __shfl_down_sync(0xffffffffu, bnv, off);
            int   oj = __shfl_down_sync(0xffffffffu, bni, off);
            if (on > bnv) { bnv = on; bni = oj; }
        }
        if (rg == 0) {
            int bucket = (bpv >= bnv) ? bpi : 64 + bni;  // pos side wins ties
            outb[((size_t)(b*HH + h)*NHH + n)*SS + tok0 + tq*4 + i] = (unsigned char)bucket;
        }
    }
}

// ---------------- 3) warp-parallel stable counting sort ---------------------
__global__ __launch_bounds__(256) void sort_kernel() {
    __shared__ unsigned char sb[SS];
    __shared__ int wcnt[8][128];
    __shared__ int woff[8][128];
    __shared__ int tot[128];
    int combo = blockIdx.x;
    int tensor = blockIdx.y;
    const unsigned char* bg = (tensor == 0 ? g_bq : g_bk) + (size_t)combo * SS;
    int t = threadIdx.x, w = t >> 5, l = t & 31;
    for (int i = t; i < SS/4; i += 256)
        ((unsigned int*)sb)[i] = ((const unsigned int*)bg)[i];
    if (t < 128) {
#pragma unroll
        for (int ww = 0; ww < 8; ww++) wcnt[ww][t] = 0;
    }
    __syncthreads();
    int seg = w * 512;
    int myb[16];
#pragma unroll
    for (int it = 0; it < 16; it++) {
        int bkt = sb[seg + it*32 + l];
        myb[it] = bkt;
        unsigned mask = __match_any_sync(0xffffffffu, (unsigned)bkt);
        if ((__ffs(mask) - 1) == l) wcnt[w][bkt] += __popc(mask);
    }
    __syncthreads();
    if (t < 128) {
        int s = 0;
#pragma unroll
        for (int ww = 0; ww < 8; ww++) s += wcnt[ww][t];
        tot[t] = s;
    }
    __syncthreads();
    if (t == 0) {
        int a = 0;
        for (int bkt = 0; bkt < 128; bkt++) { int c = tot[bkt]; tot[bkt] = a; a += c; }
    }
    __syncthreads();
    if (t < 128) {
        int run = tot[t];
#pragma unroll
        for (int ww = 0; ww < 8; ww++) { int c = wcnt[ww][t]; woff[ww][t] = run; run += c; }
    }
    __syncthreads();
    int* sorted = (tensor == 0 ? g_sq : g_sk) + (size_t)combo * SS;
    int* undo = g_undo + (size_t)combo * SS;
#pragma unroll
    for (int it = 0; it < 16; it++) {
        int p = seg + it*32 + l;
        int bkt = myb[it];
        unsigned mask = __match_any_sync(0xffffffffu, (unsigned)bkt);
        int leader = __ffs(mask) - 1;
        int rank = __popc(mask & ((1u << l) - 1u));
        int base = 0;
        if (l == leader) { base = woff[w][bkt]; woff[w][bkt] = base + __popc(mask); }
        base = __shfl_sync(mask, base, leader);
        sorted[base + rank] = p;
        if (tensor == 1) undo[p] = base + rank;
    }
}

// ---------------- 4) chunk attention (float4-quad probs layout) -------------
// QS  [row][d]        floats at QSO, row stride 64
// KT4 [dp2][j] float4 at KTO: float off = KTO + (dp2*128 + j)*4
// VT  [d][j]          floats at VTO, d stride 128
// PB4 [jq][row] f4    at PBO: float off = PBO + jq*260 + row*4 + q  (col=4jq+q, jq 0..31)
// OB  [row][d]        floats at OBO, row stride 68
#define QSO 0
#define KTO 4096
#define VTO 12288
#define PBO 0
#define PBQ 260
#define OBO 0
#define OSTR 68
#define IDXO 20480
#define SMEMF 20672

__global__ __launch_bounds__(256, 2) void attn_kernel() {
    extern __shared__ float sm[];
    int tid = threadIdx.x;
    int c = blockIdx.x;          // global chunk 0..255 (ring across rounds)
    int bh = blockIdx.y;         // b*H + h
    int n = c >> 6, cl = c & 63;
    int cp = (c + NCH - 1) & (NCH - 1);
    int np = cp >> 6, clp = cp & 63;

    const int* sq_n = g_sq + ((size_t)bh*NHH + n)*SS + cl*64;
    const int* sq_p = g_sq + ((size_t)bh*NHH + np)*SS + clp*64;
    const int* sk_n = g_sk + ((size_t)bh*NHH + n)*SS + cl*64;
    const int* sk_p = g_sk + ((size_t)bh*NHH + np)*SS + clp*64;

    int* qidx = (int*)&sm[IDXO];
    int* kidx = qidx + 64;
    if (tid < 64)       { int s = sq_n[tid]; qidx[tid] = s; kidx[64 + tid] = s; }
    else if (tid < 128) { kidx[tid - 64] = sq_p[tid - 64]; }

    // q tile [64 x 64]
    {
        int r = tid >> 2, dq = (tid & 3) * 4;
        const float* src = g_q + ((size_t)bh*SS + sq_n[r])*DD;
#pragma unroll
        for (int g = 0; g < 4; g++) {
            int d = dq + g*16;
            *(float4*)&sm[QSO + r*64 + d] = *(const float4*)&src[d];
        }
    }
    // K (normalize, dim-major float4 tiles) by threads 0..127; V^T by 128..255
    if (tid < 128) {
        int j = tid;
        int s = (j < 64) ? sk_p[j] : sk_n[j - 64];
        const float4* ksrc = (const float4*)(g_k + ((size_t)bh*SS + s)*DD);
        float ssq = 0.f;
#pragma unroll
        for (int g = 0; g < 16; g++) {
            float4 t = ksrc[g];
            ssq += t.x*t.x + t.y*t.y + t.z*t.z + t.w*t.w;
        }
        float sc = rsqrtf(ssq * (1.0f/64.0f) + 1e-6f) * 0.125f;
#pragma unroll
        for (int g = 0; g < 16; g++) {
            float4 t = ksrc[g];
            *(float4*)&sm[KTO + (g*128 + j)*4] = make_float4(t.x*sc, t.y*sc, t.z*sc, t.w*sc);
        }
    } else {
        int j = tid - 128;
        int s = (j < 64) ? sk_p[j] : sk_n[j - 64];
        const float4* vsrc = (const float4*)(g_v + ((size_t)bh*SS + s)*DD);
#pragma unroll
        for (int g = 0; g < 16; g++) {
            float4 t = vsrc[g];
            sm[VTO + (4*g+0)*128 + j] = t.x;
            sm[VTO + (4*g+1)*128 + j] = t.y;
            sm[VTO + (4*g+2)*128 + j] = t.z;
            sm[VTO + (4*g+3)*128 + j] = t.w;
        }
    }
    __syncthreads();

    int w = tid >> 5, l = tid & 31;

    // QK^T: warp w owns rows w*8..w*8+7; lane owns cols l+32*jj
    u64 acc[8][4];
#pragma unroll
    for (int i = 0; i < 8; i++)
#pragma unroll
        for (int j = 0; j < 4; j++) acc[i][j] = 0ULL;
#pragma unroll 4
    for (int dp2 = 0; dp2 < 16; dp2++) {
        ulonglong2 kk[4];
#pragma unroll
        for (int jj = 0; jj < 4; jj++)
            kk[jj] = *(const ulonglong2*)&sm[KTO + (dp2*128 + l + 32*jj)*4];
#pragma unroll
        for (int rr = 0; rr < 8; rr++) {
            ulonglong2 qq = *(const ulonglong2*)&sm[QSO + (w*8 + rr)*64 + dp2*4];
#pragma unroll
            for (int jj = 0; jj < 4; jj++) {
                fma2(acc[rr][jj], qq.x, kk[jj].x);
                fma2(acc[rr][jj], qq.y, kk[jj].y);
            }
        }
    }
    __syncthreads();   // q/k tiles free; probs region becomes writable

    // mask + softmax per row; write probs in float4-quad layout; emit logsumexp
#pragma unroll
    for (int rr = 0; rr < 8; rr++) {
        int i = w*8 + rr;
        int qi = qidx[i];
        float dv[4];
#pragma unroll
        for (int jj = 0; jj < 4; jj++) {
            float2 a = unpack2(acc[rr][jj]);
            float t = a.x + a.y;
            dv[jj] = (qi != kidx[l + 32*jj]) ? t : -1e5f;
        }
        float m = fmaxf(fmaxf(dv[0], dv[1]), fmaxf(dv[2], dv[3]));
#pragma unroll
        for (int off = 16; off; off >>= 1) m = fmaxf(m, __shfl_xor_sync(0xffffffffu, m, off));
        float p[4], ssum = 0.f;
#pragma unroll
        for (int jj = 0; jj < 4; jj++) { p[jj] = expf(dv[jj] - m); ssum += p[jj]; }
#pragma unroll
        for (int off = 16; off; off >>= 1) ssum += __shfl_xor_sync(0xffffffffu, ssum, off);
        float inv = 1.f / ssum;
#pragma unroll
        for (int jj = 0; jj < 4; jj++) {
            int cq = l + 32*jj;                 // col 0..127
            sm[PBO + (cq >> 2)*PBQ + i*4 + (cq & 3)] = p[jj] * inv;
        }
        if (l == 0) g_lsort[(size_t)bh*(NHH*SS) + c*64 + i] = logf(ssum) + m;
    }
    __syncthreads();

    // PV: lane owns rows l and l+32; warp owns dims w*8..w*8+7; jq over ALL 32 quads
    u64 o0[8], o1[8];
#pragma unroll
    for (int dd = 0; dd < 8; dd++) { o0[dd] = 0ULL; o1[dd] = 0ULL; }
#pragma unroll 4
    for (int jq = 0; jq < 32; jq++) {
        ulonglong2 pr0 = *(const ulonglong2*)&sm[PBO + jq*PBQ + l*4];
        ulonglong2 pr1 = *(const ulonglong2*)&sm[PBO + jq*PBQ + (l+32)*4];
#pragma unroll
        for (int dd = 0; dd < 8; dd++) {
            ulonglong2 vv = *(const ulonglong2*)&sm[VTO + (w*8 + dd)*128 + jq*4];
            fma2(o0[dd], pr0.x, vv.x);
            fma2(o0[dd], pr0.y, vv.y);
            fma2(o1[dd], pr1.x, vv.x);
            fma2(o1[dd], pr1.y, vv.y);
        }
    }
    __syncthreads();   // probs free; out-stage region writable
#pragma unroll
    for (int dd = 0; dd < 8; dd++) {
        float2 a = unpack2(o0[dd]); sm[OBO + l*OSTR + w*8 + dd] = a.x + a.y;
        float2 b2 = unpack2(o1[dd]); sm[OBO + (l+32)*OSTR + w*8 + dd] = b2.x + b2.y;
    }
    __syncthreads();
    {
        int r = tid >> 2, dq = (tid & 3) * 4;
        float* dst = g_osort + ((size_t)bh*(NHH*SS) + c*64 + r)*DD;
#pragma unroll
        for (int g = 0; g < 4; g++) {
            int d = dq + g*16;
            *(float4*)&dst[d] = *(const float4*)&sm[OBO + r*OSTR + d];
        }
    }
}

// ---------------- 5) key-side undo + combine rounds -------------------------
__global__ __launch_bounds__(256) void combine_kernel(float* __restrict__ out) {
    int row = blockIdx.x * 8 + (threadIdx.x >> 5);  // b*H*S rows
    int l = threadIdx.x & 31;
    int bh = row >> 12;
    int s = row & (SS - 1);
    int b = bh >> 3, h = bh & 7;
    float lg[NHH]; int up[NHH];
#pragma unroll
    for (int n = 0; n < NHH; n++) {
        int u = g_undo[((size_t)bh*NHH + n)*SS + s];
        up[n] = u;
        lg[n] = g_lsort[(size_t)bh*(NHH*SS) + n*SS + u];
    }
    float m = fmaxf(fmaxf(lg[0], lg[1]), fmaxf(lg[2], lg[3]));
    float w[NHH], wsum = 0.f;
#pragma unroll
    for (int n = 0; n < NHH; n++) { w[n] = expf(lg[n] - m); wsum += w[n]; }
    float inv = 1.f / wsum;
    float2 acc = make_float2(0.f, 0.f);
#pragma unroll
    for (int n = 0; n < NHH; n++) {
        float2 o = *(const float2*)&g_osort[((size_t)bh*(NHH*SS) + n*SS + up[n])*DD + l*2];
        acc.x += w[n]*o.x; acc.y += w[n]*o.y;
    }
    acc.x *= inv; acc.y *= inv;
    *(float2*)&out[((size_t)(b*SS + s))*(HH*DD) + h*DD + l*2] = acc;
}

// ---------------- launch -----------------------------------------------------
#define HASH_SMEM ((NHH*RSN + 64*VSS) * 4)

extern "C" void kernel_launch(void* const* d_in, const int* in_sizes, int n_in,
                              void* d_out, int out_size) {
    const float* dec = (const float*)d_in[0];
    const float* hid = (const float*)d_in[1];
    const float* wqk = (const float*)d_in[2];
    const float* wv  = (const float*)d_in[3];
    const float* rot = (const float*)d_in[4];
    float* out = (float*)d_out;

    cudaFuncSetAttribute(hash_kernel, cudaFuncAttributeMaxDynamicSharedMemorySize, HASH_SMEM);
    cudaFuncSetAttribute(attn_kernel, cudaFuncAttributeMaxDynamicSharedMemorySize, SMEMF*4);

    gemm_kernel<<<dim3(8, 64, 3), 256>>>(dec, hid, wqk, wv);
    hash_kernel<<<dim3(SS/64, HH, BB*2), 256, HASH_SMEM>>>(rot);
    sort_kernel<<<dim3(BB*HH*NHH, 2), 256>>>();
    attn_kernel<<<dim3(NCH, BB*HH), 256, SMEMF*4>>>();
    combine_kernel<<<BB*HH*SS/8, 256>>>(out);
}